// round 3
// baseline (speedup 1.0000x reference)
#include <cuda_runtime.h>

// ---------------- scratch buffers (device globals; no allocation allowed) ----
__device__ float g_q [4194304];    // [H][B*S][64]
__device__ float g_k [4194304];    // [H][B*S][64]
__device__ float g_v [33554432];   // [H][B*S][512]
__device__ float g_sc[67108864];   // [H*B][1024][1024]
__device__ float g_at[33554432];   // [B*S][4096]  (concat-head layout)
__device__ float g_mha[4194304];   // [B*S][512]
__device__ float g_h [4194304];    // [B*S][512]
__device__ float g_f1[16777216];   // [B*S][2048]
__device__ float g_f2[4194304];    // [B*S][512]

#define BM 128
#define BN 128
#define BK 16
#define TM 8
#define TN 8

// C[m,n] (+offset per z) = alpha * sum_k A[m,k] * (TB ? B[n,k] : B[k,n])
// epi: 0 = none, 1 = +bias then relu, 2 = +bias
template<bool TB>
__global__ __launch_bounds__(256)
void sgemm_kernel(const float* __restrict__ A, const float* __restrict__ B,
                  float* __restrict__ C, int M, int N, int K,
                  int lda, int ldb, int ldc,
                  long long sA, long long sB,
                  int zdiv, long long sC1, long long sC2,
                  float alpha, const float* __restrict__ bias, int epi)
{
    __shared__ float As[BK][BM];
    __shared__ float Bs[BK][BN];

    const int bz = blockIdx.z;
    A += (long long)bz * sA;
    B += (long long)bz * sB;
    const long long cOff = (long long)(bz / zdiv) * sC1 + (long long)(bz % zdiv) * sC2;

    const int mBase = blockIdx.y * BM;
    const int nBase = blockIdx.x * BN;
    const int tid   = threadIdx.x;
    const int tCol  = tid % (BN / TN);   // 0..15
    const int tRow  = tid / (BN / TN);   // 0..15

    float acc[TM][TN];
    #pragma unroll
    for (int i = 0; i < TM; i++)
        #pragma unroll
        for (int j = 0; j < TN; j++) acc[i][j] = 0.0f;

    for (int k0 = 0; k0 < K; k0 += BK) {
        // ---- load A tile (BM x BK), 512 float4 / 256 threads = 2 each ----
        #pragma unroll
        for (int it = 0; it < 2; it++) {
            int idx = tid + it * 256;            // 0..511
            int r   = idx >> 2;                  // 0..127
            int c4  = idx & 3;                   // 0..3 (BK/4)
            float4 v = *(const float4*)(A + (long long)(mBase + r) * lda + k0 + c4 * 4);
            As[c4 * 4 + 0][r] = v.x;
            As[c4 * 4 + 1][r] = v.y;
            As[c4 * 4 + 2][r] = v.z;
            As[c4 * 4 + 3][r] = v.w;
        }
        // ---- load B tile (BK x BN) ----
        if (!TB) {
            #pragma unroll
            for (int it = 0; it < 2; it++) {
                int idx = tid + it * 256;
                int r   = idx >> 5;              // 0..15  (BN/4 = 32 per row)
                int c4  = idx & 31;
                int n   = nBase + c4 * 4;
                float4 v = (n < N) ? *(const float4*)(B + (long long)(k0 + r) * ldb + n)
                                   : make_float4(0.f, 0.f, 0.f, 0.f);
                *(float4*)&Bs[r][c4 * 4] = v;
            }
        } else {
            #pragma unroll
            for (int it = 0; it < 2; it++) {
                int idx = tid + it * 256;
                int n   = idx >> 2;              // 0..127
                int c4  = idx & 3;
                int gn  = nBase + n;
                float4 v = (gn < N) ? *(const float4*)(B + (long long)gn * ldb + k0 + c4 * 4)
                                    : make_float4(0.f, 0.f, 0.f, 0.f);
                Bs[c4 * 4 + 0][n] = v.x;
                Bs[c4 * 4 + 1][n] = v.y;
                Bs[c4 * 4 + 2][n] = v.z;
                Bs[c4 * 4 + 3][n] = v.w;
            }
        }
        __syncthreads();

        // ---- compute ----
        #pragma unroll
        for (int k = 0; k < BK; k++) {
            float4 a0 = *(const float4*)&As[k][tRow * TM];
            float4 a1 = *(const float4*)&As[k][tRow * TM + 4];
            float4 b0 = *(const float4*)&Bs[k][tCol * TN];
            float4 b1 = *(const float4*)&Bs[k][tCol * TN + 4];
            float ar[TM] = {a0.x, a0.y, a0.z, a0.w, a1.x, a1.y, a1.z, a1.w};
            float br[TN] = {b0.x, b0.y, b0.z, b0.w, b1.x, b1.y, b1.z, b1.w};
            #pragma unroll
            for (int i = 0; i < TM; i++)
                #pragma unroll
                for (int j = 0; j < TN; j++)
                    acc[i][j] += ar[i] * br[j];
        }
        __syncthreads();
    }

    // ---- epilogue ----
    #pragma unroll
    for (int i = 0; i < TM; i++) {
        int m = mBase + tRow * TM + i;
        #pragma unroll
        for (int j0 = 0; j0 < TN; j0 += 4) {
            int n = nBase + tCol * TN + j0;
            if (n < N) {
                float4 o;
                o.x = acc[i][j0 + 0] * alpha;
                o.y = acc[i][j0 + 1] * alpha;
                o.z = acc[i][j0 + 2] * alpha;
                o.w = acc[i][j0 + 3] * alpha;
                if (epi != 0) {
                    const float4 bb = *(const float4*)(bias + n);
                    o.x += bb.x; o.y += bb.y; o.z += bb.z; o.w += bb.w;
                    if (epi == 1) {
                        o.x = fmaxf(o.x, 0.f); o.y = fmaxf(o.y, 0.f);
                        o.z = fmaxf(o.z, 0.f); o.w = fmaxf(o.w, 0.f);
                    }
                }
                *(float4*)(C + cOff + (long long)m * ldc + n) = o;
            }
        }
    }
}

// row softmax over rows of length 1024; one block (256 thr) per row, in place
__global__ __launch_bounds__(256)
void softmax1024(float* __restrict__ S)
{
    __shared__ float red[8];
    float* p = S + (long long)blockIdx.x * 1024;
    const int tid = threadIdx.x;

    float4 v = reinterpret_cast<float4*>(p)[tid];
    float m = fmaxf(fmaxf(v.x, v.y), fmaxf(v.z, v.w));
    #pragma unroll
    for (int o = 16; o > 0; o >>= 1) m = fmaxf(m, __shfl_xor_sync(0xffffffffu, m, o));
    if ((tid & 31) == 0) red[tid >> 5] = m;
    __syncthreads();
    m = fmaxf(fmaxf(fmaxf(red[0], red[1]), fmaxf(red[2], red[3])),
              fmaxf(fmaxf(red[4], red[5]), fmaxf(red[6], red[7])));
    __syncthreads();

    v.x = __expf(v.x - m); v.y = __expf(v.y - m);
    v.z = __expf(v.z - m); v.w = __expf(v.w - m);
    float s = (v.x + v.y) + (v.z + v.w);
    #pragma unroll
    for (int o = 16; o > 0; o >>= 1) s += __shfl_xor_sync(0xffffffffu, s, o);
    if ((tid & 31) == 0) red[tid >> 5] = s;
    __syncthreads();
    s = ((red[0] + red[1]) + (red[2] + red[3])) + ((red[4] + red[5]) + (red[6] + red[7]));

    const float inv = 1.0f / s;
    v.x *= inv; v.y *= inv; v.z *= inv; v.w *= inv;
    reinterpret_cast<float4*>(p)[tid] = v;
}

// O[row] = LayerNorm(X[row] + Y[row]) ; rows of 512, 128 threads/row
__global__ __launch_bounds__(128)
void add_ln512(const float* __restrict__ X, const float* __restrict__ Y,
               const float* __restrict__ gamma, const float* __restrict__ beta,
               float* __restrict__ O)
{
    __shared__ float red[4];
    const long long row = blockIdx.x;
    const int tid = threadIdx.x;   // 0..127

    const float4 x4 = ((const float4*)(X + row * 512))[tid];
    const float4 y4 = ((const float4*)(Y + row * 512))[tid];
    float4 v;
    v.x = x4.x + y4.x; v.y = x4.y + y4.y; v.z = x4.z + y4.z; v.w = x4.w + y4.w;

    float s = (v.x + v.y) + (v.z + v.w);
    #pragma unroll
    for (int o = 16; o > 0; o >>= 1) s += __shfl_xor_sync(0xffffffffu, s, o);
    if ((tid & 31) == 0) red[tid >> 5] = s;
    __syncthreads();
    const float mean = ((red[0] + red[1]) + (red[2] + red[3])) * (1.0f / 512.0f);
    __syncthreads();

    float q = v.x * v.x + v.y * v.y + v.z * v.z + v.w * v.w;
    #pragma unroll
    for (int o = 16; o > 0; o >>= 1) q += __shfl_xor_sync(0xffffffffu, q, o);
    if ((tid & 31) == 0) red[tid >> 5] = q;
    __syncthreads();
    const float var = ((red[0] + red[1]) + (red[2] + red[3])) * (1.0f / 512.0f) - mean * mean;
    const float inv = rsqrtf(var + 1e-3f);

    const int n = tid * 4;
    const float4 g4 = *(const float4*)(gamma + n);
    const float4 b4 = *(const float4*)(beta + n);
    float4 o;
    o.x = g4.x * (v.x - mean) * inv + b4.x;
    o.y = g4.y * (v.y - mean) * inv + b4.y;
    o.z = g4.z * (v.z - mean) * inv + b4.z;
    o.w = g4.w * (v.w - mean) * inv + b4.w;
    ((float4*)(O + row * 512))[tid] = o;
}

// ---------------------------------------------------------------------------

static void run_gemm(bool tb, const float* A, const float* B, float* C,
                     int M, int N, int K, int lda, int ldb, int ldc,
                     long long sA, long long sB,
                     int zdiv, long long sC1, long long sC2,
                     int batch, float alpha, const float* bias, int epi)
{
    dim3 grid((N + BN - 1) / BN, (M + BM - 1) / BM, batch);
    if (tb)
        sgemm_kernel<true><<<grid, 256>>>(A, B, C, M, N, K, lda, ldb, ldc,
                                          sA, sB, zdiv, sC1, sC2, alpha, bias, epi);
    else
        sgemm_kernel<false><<<grid, 256>>>(A, B, C, M, N, K, lda, ldb, ldc,
                                           sA, sB, zdiv, sC1, sC2, alpha, bias, epi);
}

struct Scratch {
    float *q, *k, *v, *sc, *at, *mha, *h, *f1, *f2;
};

static Scratch get_scratch()
{
    static Scratch s;
    static bool init = false;
    if (!init) {
        cudaGetSymbolAddress((void**)&s.q,   g_q);
        cudaGetSymbolAddress((void**)&s.k,   g_k);
        cudaGetSymbolAddress((void**)&s.v,   g_v);
        cudaGetSymbolAddress((void**)&s.sc,  g_sc);
        cudaGetSymbolAddress((void**)&s.at,  g_at);
        cudaGetSymbolAddress((void**)&s.mha, g_mha);
        cudaGetSymbolAddress((void**)&s.h,   g_h);
        cudaGetSymbolAddress((void**)&s.f1,  g_f1);
        cudaGetSymbolAddress((void**)&s.f2,  g_f2);
        init = true;
    }
    return s;
}

extern "C" void kernel_launch(void* const* d_in, const int* in_sizes, int n_in,
                              void* d_out, int out_size)
{
    const float* x      = (const float*)d_in[0];   // [8,1024,512]
    const float* qw     = (const float*)d_in[1];   // [8,512,64]
    const float* kw     = (const float*)d_in[2];   // [8,512,64]
    const float* vw     = (const float*)d_in[3];   // [8,512,512]
    const float* lw     = (const float*)d_in[4];   // [4096,512]
    const float* gamma1 = (const float*)d_in[5];
    const float* beta1  = (const float*)d_in[6];
    const float* w1     = (const float*)d_in[7];   // [512,2048]
    const float* b1     = (const float*)d_in[8];
    const float* w2     = (const float*)d_in[9];   // [2048,512]
    const float* b2     = (const float*)d_in[10];
    const float* gamma2 = (const float*)d_in[11];
    const float* beta2  = (const float*)d_in[12];
    float* out = (float*)d_out;

    Scratch s = get_scratch();

    const int M = 8192;                 // B*S
    const float scale = 0.044194173824159216f;  // 1/sqrt(512)

    // Q = x @ qw[h]  -> g_q [H][M][64]
    run_gemm(false, x, qw, s.q, M, 64, 512, 512, 64, 64,
             0LL, 512LL * 64, 1, 8192LL * 64, 0LL, 8, 1.0f, nullptr, 0);
    // K = x @ kw[h]  -> g_k [H][M][64]
    run_gemm(false, x, kw, s.k, M, 64, 512, 512, 64, 64,
             0LL, 512LL * 64, 1, 8192LL * 64, 0LL, 8, 1.0f, nullptr, 0);
    // V = x @ vw[h]  -> g_v [H][M][512]
    run_gemm(false, x, vw, s.v, M, 512, 512, 512, 512, 512,
             0LL, 512LL * 512, 1, 8192LL * 512, 0LL, 8, 1.0f, nullptr, 0);

    // scores[z=h*8+b] = scale * Q_z @ K_z^T   (1024x1024, K=64)
    run_gemm(true, s.q, s.k, s.sc, 1024, 1024, 64, 64, 64, 1024,
             65536LL, 65536LL, 1, 1048576LL, 0LL, 64, scale, nullptr, 0);

    softmax1024<<<65536, 256>>>(s.sc);

    // attn[z] = P_z @ V_z -> g_at[m][h*512 + e]  (z = h*8+b)
    run_gemm(false, s.sc, s.v, s.at, 1024, 512, 1024, 1024, 512, 4096,
             1048576LL, 524288LL, 8, 512LL, 4194304LL, 64, 1.0f, nullptr, 0);

    // mha = attn_concat @ lw
    run_gemm(false, s.at, lw, s.mha, M, 512, 4096, 4096, 512, 512,
             0LL, 0LL, 1, 0LL, 0LL, 1, 1.0f, nullptr, 0);

    // h = LN(x + mha)
    add_ln512<<<8192, 128>>>(x, s.mha, gamma1, beta1, s.h);

    // f1 = relu(h @ w1 + b1)
    run_gemm(false, s.h, w1, s.f1, M, 2048, 512, 512, 2048, 2048,
             0LL, 0LL, 1, 0LL, 0LL, 1, 1.0f, b1, 1);
    // f2 = f1 @ w2 + b2
    run_gemm(false, s.f1, w2, s.f2, M, 512, 2048, 2048, 512, 512,
             0LL, 0LL, 1, 0LL, 0LL, 1, 1.0f, b2, 2);

    // out = LN(h + f2)
    add_ln512<<<8192, 128>>>(s.h, s.f2, gamma2, beta2, out);
}

// round 4
// speedup vs baseline: 1.6452x; 1.6452x over previous
#include <cuda_runtime.h>
#include <cuda_bf16.h>
#include <cstdint>

// ---------------- scratch buffers (device globals; no allocation allowed) ----
__device__ float g_q [4194304];    // [H][B*S][64]
__device__ float g_k [4194304];    // [H][B*S][64]
__device__ float g_v [33554432];   // [H][B*S][512]
__device__ float g_sc[67108864];   // [H*B][1024][1024]
__device__ float g_at[33554432];   // [B*S][4096]  (concat-head layout)
__device__ float g_mha[4194304];   // [B*S][512]
__device__ float g_h [4194304];    // [B*S][512]
__device__ float g_f1[16777216];   // [B*S][2048]
__device__ float g_f2[4194304];    // [B*S][512]

#define BM 128
#define BN 128
#define BKK 32
#define ASTR 40          // A smem row stride (halves): conflict-free for ldmatrix
#define BSTR_NM 40       // B smem stride, n-major layout (TB)
#define BSTR_KM 136      // B smem stride, k-major layout (!TB)

__device__ __forceinline__ void ldsm4(uint32_t* r, uint32_t addr) {
    asm volatile("ldmatrix.sync.aligned.m8n8.x4.shared.b16 {%0,%1,%2,%3},[%4];"
                 : "=r"(r[0]), "=r"(r[1]), "=r"(r[2]), "=r"(r[3]) : "r"(addr));
}
__device__ __forceinline__ void ldsm2(uint32_t* r, uint32_t addr) {
    asm volatile("ldmatrix.sync.aligned.m8n8.x2.shared.b16 {%0,%1},[%2];"
                 : "=r"(r[0]), "=r"(r[1]) : "r"(addr));
}
__device__ __forceinline__ void ldsm2t(uint32_t* r, uint32_t addr) {
    asm volatile("ldmatrix.sync.aligned.m8n8.x2.trans.shared.b16 {%0,%1},[%2];"
                 : "=r"(r[0]), "=r"(r[1]) : "r"(addr));
}
__device__ __forceinline__ void mma16816(float* c, const uint32_t* a, const uint32_t* b) {
    asm volatile(
        "mma.sync.aligned.m16n8k16.row.col.f32.bf16.bf16.f32 "
        "{%0,%1,%2,%3},{%4,%5,%6,%7},{%8,%9},{%0,%1,%2,%3};"
        : "+f"(c[0]), "+f"(c[1]), "+f"(c[2]), "+f"(c[3])
        : "r"(a[0]), "r"(a[1]), "r"(a[2]), "r"(a[3]), "r"(b[0]), "r"(b[1]));
}

__device__ __forceinline__ void split2(float x, __nv_bfloat16& h, __nv_bfloat16& l) {
    h = __float2bfloat16(x);
    l = __float2bfloat16(x - __bfloat162float(h));
}

// C[m,n] (+offset per z) = alpha * sum_k A[m,k] * (TB ? B[n,k] : B[k,n])
// epi: 0 = none, 1 = +bias then relu, 2 = +bias
// Requires: M % 128 == 0, K % 32 == 0, N % 4 == 0.
template<bool TB>
__global__ __launch_bounds__(256)
void mma_gemm(const float* __restrict__ A, const float* __restrict__ B,
              float* __restrict__ C, int M, int N, int K,
              int lda, int ldb, int ldc,
              long long sA, long long sB,
              int zdiv, long long sC1, long long sC2,
              float alpha, const float* __restrict__ bias, int epi)
{
    constexpr int APLANE = 128 * ASTR;                       // halves per hi/lo plane
    constexpr int BPLANE = TB ? 128 * BSTR_NM : 32 * BSTR_KM;

    __shared__ __nv_bfloat16 As[2 * APLANE];
    __shared__ __nv_bfloat16 Bs[2 * BPLANE];

    const int bz = blockIdx.z;
    A += (long long)bz * sA;
    B += (long long)bz * sB;
    const long long cOff = (long long)(bz / zdiv) * sC1 + (long long)(bz % zdiv) * sC2;

    const int mBase = blockIdx.y * BM;
    const int nBase = blockIdx.x * BN;
    const int tid   = threadIdx.x;
    const int lane  = tid & 31;
    const int warp  = tid >> 5;
    const int wm    = warp >> 2;     // 0..1  -> 64 rows
    const int wn    = warp & 3;      // 0..3  -> 32 cols

    const uint32_t asU = (uint32_t)__cvta_generic_to_shared(As);
    const uint32_t bsU = (uint32_t)__cvta_generic_to_shared(Bs);

    // ldmatrix lane address components
    const int aRow = (lane & 7) | (((lane >> 3) & 1) << 3);  // row within 16
    const int aK   = (lane >> 4) << 3;                        // 0 or 8
    const int blane = lane & 15;

    float acc[4][4][4];
    #pragma unroll
    for (int i = 0; i < 4; i++)
        #pragma unroll
        for (int j = 0; j < 4; j++)
            #pragma unroll
            for (int e = 0; e < 4; e++) acc[i][j][e] = 0.0f;

    for (int k0 = 0; k0 < K; k0 += BKK) {
        // ---- load + split A tile (128 x 32) ----
        #pragma unroll
        for (int it = 0; it < 4; it++) {
            int idx = tid + it * 256;           // 0..1023
            int r   = idx >> 3;                 // 0..127
            int c   = (idx & 7) << 2;           // 0..28
            float4 v = *(const float4*)(A + (long long)(mBase + r) * lda + k0 + c);
            __nv_bfloat16 h0, h1, h2, h3, l0, l1, l2, l3;
            split2(v.x, h0, l0); split2(v.y, h1, l1);
            split2(v.z, h2, l2); split2(v.w, h3, l3);
            int off = r * ASTR + c;
            *(__nv_bfloat162*)&As[off]              = __halves2bfloat162(h0, h1);
            *(__nv_bfloat162*)&As[off + 2]          = __halves2bfloat162(h2, h3);
            *(__nv_bfloat162*)&As[APLANE + off]     = __halves2bfloat162(l0, l1);
            *(__nv_bfloat162*)&As[APLANE + off + 2] = __halves2bfloat162(l2, l3);
        }
        // ---- load + split B tile ----
        if (TB) {
            // B[n][k] row-major -> Bs n-major [128][BSTR_NM]
            #pragma unroll
            for (int it = 0; it < 4; it++) {
                int idx = tid + it * 256;
                int r   = idx >> 3;             // n local 0..127
                int c   = (idx & 7) << 2;       // k local
                int gn  = nBase + r;
                float4 v = (gn < N) ? *(const float4*)(B + (long long)gn * ldb + k0 + c)
                                    : make_float4(0.f, 0.f, 0.f, 0.f);
                __nv_bfloat16 h0, h1, h2, h3, l0, l1, l2, l3;
                split2(v.x, h0, l0); split2(v.y, h1, l1);
                split2(v.z, h2, l2); split2(v.w, h3, l3);
                int off = r * BSTR_NM + c;
                *(__nv_bfloat162*)&Bs[off]              = __halves2bfloat162(h0, h1);
                *(__nv_bfloat162*)&Bs[off + 2]          = __halves2bfloat162(h2, h3);
                *(__nv_bfloat162*)&Bs[BPLANE + off]     = __halves2bfloat162(l0, l1);
                *(__nv_bfloat162*)&Bs[BPLANE + off + 2] = __halves2bfloat162(l2, l3);
            }
        } else {
            // B[k][n] row-major -> Bs k-major [32][BSTR_KM]
            #pragma unroll
            for (int it = 0; it < 4; it++) {
                int idx = tid + it * 256;
                int r   = idx >> 5;             // k local 0..31
                int nl  = (idx & 31) << 2;      // n local 0..124
                int gn  = nBase + nl;
                float4 v = (gn < N) ? *(const float4*)(B + (long long)(k0 + r) * ldb + gn)
                                    : make_float4(0.f, 0.f, 0.f, 0.f);
                __nv_bfloat16 h0, h1, h2, h3, l0, l1, l2, l3;
                split2(v.x, h0, l0); split2(v.y, h1, l1);
                split2(v.z, h2, l2); split2(v.w, h3, l3);
                int off = r * BSTR_KM + nl;
                *(__nv_bfloat162*)&Bs[off]              = __halves2bfloat162(h0, h1);
                *(__nv_bfloat162*)&Bs[off + 2]          = __halves2bfloat162(h2, h3);
                *(__nv_bfloat162*)&Bs[BPLANE + off]     = __halves2bfloat162(l0, l1);
                *(__nv_bfloat162*)&Bs[BPLANE + off + 2] = __halves2bfloat162(l2, l3);
            }
        }
        __syncthreads();

        // ---- compute: 2 k-steps of 16 ----
        #pragma unroll
        for (int ks = 0; ks < 2; ks++) {
            uint32_t bh[4][2], blo[4][2];
            #pragma unroll
            for (int ni = 0; ni < 4; ni++) {
                uint32_t baddr;
                if (TB) {
                    int off = (wn * 32 + ni * 8 + (blane & 7)) * BSTR_NM
                            + ks * 16 + ((blane >> 3) << 3);
                    baddr = bsU + off * 2;
                    ldsm2(bh[ni], baddr);
                    ldsm2(blo[ni], baddr + BPLANE * 2);
                } else {
                    int off = (ks * 16 + blane) * BSTR_KM + wn * 32 + ni * 8;
                    baddr = bsU + off * 2;
                    ldsm2t(bh[ni], baddr);
                    ldsm2t(blo[ni], baddr + BPLANE * 2);
                }
            }
            #pragma unroll
            for (int mi = 0; mi < 4; mi++) {
                uint32_t ah[4], al[4];
                int off = (wm * 64 + mi * 16 + aRow) * ASTR + ks * 16 + aK;
                uint32_t aaddr = asU + off * 2;
                ldsm4(ah, aaddr);
                ldsm4(al, aaddr + APLANE * 2);
                #pragma unroll
                for (int ni = 0; ni < 4; ni++) {
                    mma16816(acc[mi][ni], ah, bh[ni]);   // hi*hi
                    mma16816(acc[mi][ni], ah, blo[ni]);  // hi*lo
                    mma16816(acc[mi][ni], al, bh[ni]);   // lo*hi
                }
            }
        }
        __syncthreads();
    }

    // ---- epilogue ----
    const int g   = lane >> 2;
    const int tig = lane & 3;
    #pragma unroll
    for (int mi = 0; mi < 4; mi++) {
        #pragma unroll
        for (int ni = 0; ni < 4; ni++) {
            int n = nBase + wn * 32 + ni * 8 + tig * 2;
            if (n < N) {
                float bx = 0.f, by = 0.f;
                if (epi != 0) { bx = bias[n]; by = bias[n + 1]; }
                #pragma unroll
                for (int rr = 0; rr < 2; rr++) {
                    int m = mBase + wm * 64 + mi * 16 + g + rr * 8;
                    float2 o;
                    o.x = acc[mi][ni][rr * 2 + 0] * alpha + bx;
                    o.y = acc[mi][ni][rr * 2 + 1] * alpha + by;
                    if (epi == 1) { o.x = fmaxf(o.x, 0.f); o.y = fmaxf(o.y, 0.f); }
                    *(float2*)(C + cOff + (long long)m * ldc + n) = o;
                }
            }
        }
    }
}

// row softmax over rows of length 1024; one block (256 thr) per row, in place
__global__ __launch_bounds__(256)
void softmax1024(float* __restrict__ S)
{
    __shared__ float red[8];
    float* p = S + (long long)blockIdx.x * 1024;
    const int tid = threadIdx.x;

    float4 v = reinterpret_cast<float4*>(p)[tid];
    float m = fmaxf(fmaxf(v.x, v.y), fmaxf(v.z, v.w));
    #pragma unroll
    for (int o = 16; o > 0; o >>= 1) m = fmaxf(m, __shfl_xor_sync(0xffffffffu, m, o));
    if ((tid & 31) == 0) red[tid >> 5] = m;
    __syncthreads();
    m = fmaxf(fmaxf(fmaxf(red[0], red[1]), fmaxf(red[2], red[3])),
              fmaxf(fmaxf(red[4], red[5]), fmaxf(red[6], red[7])));
    __syncthreads();

    v.x = __expf(v.x - m); v.y = __expf(v.y - m);
    v.z = __expf(v.z - m); v.w = __expf(v.w - m);
    float s = (v.x + v.y) + (v.z + v.w);
    #pragma unroll
    for (int o = 16; o > 0; o >>= 1) s += __shfl_xor_sync(0xffffffffu, s, o);
    if ((tid & 31) == 0) red[tid >> 5] = s;
    __syncthreads();
    s = ((red[0] + red[1]) + (red[2] + red[3])) + ((red[4] + red[5]) + (red[6] + red[7]));

    const float inv = 1.0f / s;
    v.x *= inv; v.y *= inv; v.z *= inv; v.w *= inv;
    reinterpret_cast<float4*>(p)[tid] = v;
}

// O[row] = LayerNorm(X[row] + Y[row]) ; rows of 512, 128 threads/row
__global__ __launch_bounds__(128)
void add_ln512(const float* __restrict__ X, const float* __restrict__ Y,
               const float* __restrict__ gamma, const float* __restrict__ beta,
               float* __restrict__ O)
{
    __shared__ float red[4];
    const long long row = blockIdx.x;
    const int tid = threadIdx.x;   // 0..127

    const float4 x4 = ((const float4*)(X + row * 512))[tid];
    const float4 y4 = ((const float4*)(Y + row * 512))[tid];
    float4 v;
    v.x = x4.x + y4.x; v.y = x4.y + y4.y; v.z = x4.z + y4.z; v.w = x4.w + y4.w;

    float s = (v.x + v.y) + (v.z + v.w);
    #pragma unroll
    for (int o = 16; o > 0; o >>= 1) s += __shfl_xor_sync(0xffffffffu, s, o);
    if ((tid & 31) == 0) red[tid >> 5] = s;
    __syncthreads();
    const float mean = ((red[0] + red[1]) + (red[2] + red[3])) * (1.0f / 512.0f);
    __syncthreads();

    float q = v.x * v.x + v.y * v.y + v.z * v.z + v.w * v.w;
    #pragma unroll
    for (int o = 16; o > 0; o >>= 1) q += __shfl_xor_sync(0xffffffffu, q, o);
    if ((tid & 31) == 0) red[tid >> 5] = q;
    __syncthreads();
    const float var = ((red[0] + red[1]) + (red[2] + red[3])) * (1.0f / 512.0f) - mean * mean;
    const float inv = rsqrtf(var + 1e-3f);

    const int n = tid * 4;
    const float4 g4 = *(const float4*)(gamma + n);
    const float4 b4 = *(const float4*)(beta + n);
    float4 o;
    o.x = g4.x * (v.x - mean) * inv + b4.x;
    o.y = g4.y * (v.y - mean) * inv + b4.y;
    o.z = g4.z * (v.z - mean) * inv + b4.z;
    o.w = g4.w * (v.w - mean) * inv + b4.w;
    ((float4*)(O + row * 512))[tid] = o;
}

// ---------------------------------------------------------------------------

static void run_gemm(bool tb, const float* A, const float* B, float* C,
                     int M, int N, int K, int lda, int ldb, int ldc,
                     long long sA, long long sB,
                     int zdiv, long long sC1, long long sC2,
                     int batch, float alpha, const float* bias, int epi)
{
    dim3 grid((N + BN - 1) / BN, (M + BM - 1) / BM, batch);
    if (tb)
        mma_gemm<true><<<grid, 256>>>(A, B, C, M, N, K, lda, ldb, ldc,
                                      sA, sB, zdiv, sC1, sC2, alpha, bias, epi);
    else
        mma_gemm<false><<<grid, 256>>>(A, B, C, M, N, K, lda, ldb, ldc,
                                       sA, sB, zdiv, sC1, sC2, alpha, bias, epi);
}

struct Scratch {
    float *q, *k, *v, *sc, *at, *mha, *h, *f1, *f2;
};

static Scratch get_scratch()
{
    static Scratch s;
    static bool init = false;
    if (!init) {
        cudaGetSymbolAddress((void**)&s.q,   g_q);
        cudaGetSymbolAddress((void**)&s.k,   g_k);
        cudaGetSymbolAddress((void**)&s.v,   g_v);
        cudaGetSymbolAddress((void**)&s.sc,  g_sc);
        cudaGetSymbolAddress((void**)&s.at,  g_at);
        cudaGetSymbolAddress((void**)&s.mha, g_mha);
        cudaGetSymbolAddress((void**)&s.h,   g_h);
        cudaGetSymbolAddress((void**)&s.f1,  g_f1);
        cudaGetSymbolAddress((void**)&s.f2,  g_f2);
        init = true;
    }
    return s;
}

extern "C" void kernel_launch(void* const* d_in, const int* in_sizes, int n_in,
                              void* d_out, int out_size)
{
    const float* x      = (const float*)d_in[0];   // [8,1024,512]
    const float* qw     = (const float*)d_in[1];   // [8,512,64]
    const float* kw     = (const float*)d_in[2];   // [8,512,64]
    const float* vw     = (const float*)d_in[3];   // [8,512,512]
    const float* lw     = (const float*)d_in[4];   // [4096,512]
    const float* gamma1 = (const float*)d_in[5];
    const float* beta1  = (const float*)d_in[6];
    const float* w1     = (const float*)d_in[7];   // [512,2048]
    const float* b1     = (const float*)d_in[8];
    const float* w2     = (const float*)d_in[9];   // [2048,512]
    const float* b2     = (const float*)d_in[10];
    const float* gamma2 = (const float*)d_in[11];
    const float* beta2  = (const float*)d_in[12];
    float* out = (float*)d_out;

    Scratch s = get_scratch();

    const int M = 8192;                 // B*S
    const float scale = 0.044194173824159216f;  // 1/sqrt(512)

    // Q = x @ qw[h]  -> g_q [H][M][64]
    run_gemm(false, x, qw, s.q, M, 64, 512, 512, 64, 64,
             0LL, 512LL * 64, 1, 8192LL * 64, 0LL, 8, 1.0f, nullptr, 0);
    // K = x @ kw[h]  -> g_k [H][M][64]
    run_gemm(false, x, kw, s.k, M, 64, 512, 512, 64, 64,
             0LL, 512LL * 64, 1, 8192LL * 64, 0LL, 8, 1.0f, nullptr, 0);
    // V = x @ vw[h]  -> g_v [H][M][512]
    run_gemm(false, x, vw, s.v, M, 512, 512, 512, 512, 512,
             0LL, 512LL * 512, 1, 8192LL * 512, 0LL, 8, 1.0f, nullptr, 0);

    // scores[z=h*8+b] = scale * Q_z @ K_z^T   (1024x1024, K=64)
    run_gemm(true, s.q, s.k, s.sc, 1024, 1024, 64, 64, 64, 1024,
             65536LL, 65536LL, 1, 1048576LL, 0LL, 64, scale, nullptr, 0);

    softmax1024<<<65536, 256>>>(s.sc);

    // attn[z] = P_z @ V_z -> g_at[m][h*512 + e]  (z = h*8+b)
    run_gemm(false, s.sc, s.v, s.at, 1024, 512, 1024, 1024, 512, 4096,
             1048576LL, 524288LL, 8, 512LL, 4194304LL, 64, 1.0f, nullptr, 0);

    // mha = attn_concat @ lw
    run_gemm(false, s.at, lw, s.mha, M, 512, 4096, 4096, 512, 512,
             0LL, 0LL, 1, 0LL, 0LL, 1, 1.0f, nullptr, 0);

    // h = LN(x + mha)
    add_ln512<<<8192, 128>>>(x, s.mha, gamma1, beta1, s.h);

    // f1 = relu(h @ w1 + b1)
    run_gemm(false, s.h, w1, s.f1, M, 2048, 512, 512, 2048, 2048,
             0LL, 0LL, 1, 0LL, 0LL, 1, 1.0f, b1, 1);
    // f2 = f1 @ w2 + b2
    run_gemm(false, s.f1, w2, s.f2, M, 512, 2048, 2048, 512, 512,
             0LL, 0LL, 1, 0LL, 0LL, 1, 1.0f, b2, 2);

    // out = LN(h + f2)
    add_ln512<<<8192, 128>>>(s.h, s.f2, gamma2, beta2, out);
}

// round 6
// speedup vs baseline: 2.6972x; 1.6395x over previous
#include <cuda_runtime.h>
#include <cuda_bf16.h>
#include <cstdint>

typedef __nv_bfloat16  bf16;
typedef __nv_bfloat162 bf162;

// ---------------- scratch (device globals; no allocation allowed) -----------
__device__ float g_sc [67108864];   // [64][1024][1024] fp32 scores
__device__ float g_mha[4194304];    // [8192][512]
__device__ float g_h  [4194304];    // [8192][512]
__device__ float g_f2 [4194304];    // [8192][512]

// bf16 hi/lo plane pairs (hi at 0, lo at +plane)
__device__ bf16 g_xs [8388608];     // x      plane 4194304
__device__ bf16 g_qws[524288];      // qw     plane 262144
__device__ bf16 g_kws[524288];      // kw     plane 262144
__device__ bf16 g_vws[4194304];     // vw     plane 2097152
__device__ bf16 g_lws[4194304];     // lw     plane 2097152
__device__ bf16 g_w1s[2097152];     // w1     plane 1048576
__device__ bf16 g_w2s[2097152];     // w2     plane 1048576
__device__ bf16 g_qs [8388608];     // q      plane 4194304   [H][8192][64]
__device__ bf16 g_ks [8388608];     // k      plane 4194304
__device__ bf16 g_vs [67108864];    // v      plane 33554432  [H][8192][512]
__device__ bf16 g_ps [134217728];   // probs  plane 67108864  [64][1024][1024]
__device__ bf16 g_ats[67108864];    // attn   plane 33554432  [8192][4096]
__device__ bf16 g_hs [8388608];     // h      plane 4194304
__device__ bf16 g_f1s[33554432];    // f1     plane 16777216  [8192][2048]

#define BM 128
#define BN 128

// smem layout (bytes): A bufs at 0, B bufs at 40960
#define APL_B   10240     // A plane bytes (128*40 halves)
#define ABUF_B  20480
#define BOFF_B  40960
#define BPL_TB  10240     // B plane bytes, n-major (128*40)
#define BBUF_TB 20480
#define BPL_KM  8704      // B plane bytes, k-major (32*136)
#define BBUF_KM 17408
#define SMEM_BYTES 81920

__device__ __forceinline__ void ldsm4(uint32_t* r, uint32_t addr) {
    asm volatile("ldmatrix.sync.aligned.m8n8.x4.shared.b16 {%0,%1,%2,%3},[%4];"
                 : "=r"(r[0]), "=r"(r[1]), "=r"(r[2]), "=r"(r[3]) : "r"(addr));
}
__device__ __forceinline__ void ldsm2(uint32_t* r, uint32_t addr) {
    asm volatile("ldmatrix.sync.aligned.m8n8.x2.shared.b16 {%0,%1},[%2];"
                 : "=r"(r[0]), "=r"(r[1]) : "r"(addr));
}
__device__ __forceinline__ void ldsm2t(uint32_t* r, uint32_t addr) {
    asm volatile("ldmatrix.sync.aligned.m8n8.x2.trans.shared.b16 {%0,%1},[%2];"
                 : "=r"(r[0]), "=r"(r[1]) : "r"(addr));
}
__device__ __forceinline__ void mma16816(float* c, const uint32_t* a, const uint32_t* b) {
    asm volatile(
        "mma.sync.aligned.m16n8k16.row.col.f32.bf16.bf16.f32 "
        "{%0,%1,%2,%3},{%4,%5,%6,%7},{%8,%9},{%0,%1,%2,%3};"
        : "+f"(c[0]), "+f"(c[1]), "+f"(c[2]), "+f"(c[3])
        : "r"(a[0]), "r"(a[1]), "r"(a[2]), "r"(a[3]), "r"(b[0]), "r"(b[1]));
}
__device__ __forceinline__ void cp16(uint32_t dst, const void* src) {
    asm volatile("cp.async.cg.shared.global [%0], [%1], 16;" :: "r"(dst), "l"(src));
}
__device__ __forceinline__ void cp16z(uint32_t dst, const void* src) {
    asm volatile("cp.async.cg.shared.global [%0], [%1], 16, %2;"
                 :: "r"(dst), "l"(src), "r"(0));
}
__device__ __forceinline__ void split2(float x, bf16& h, bf16& l) {
    h = __float2bfloat16(x);
    l = __float2bfloat16(x - __bfloat162float(h));
}

// C = alpha * A @ (TB ? B^T : B) (+bias)(relu); A,B are bf16 hi/lo plane pairs.
// Output: fp32 to Cf and/or split bf16 planes to Cs.
// Requires M%128==0, K%32==0, N%8==0; B k-major cols beyond N are zero-filled.
template<bool TB>
__global__ __launch_bounds__(256, 2)
void mma_gemm(const bf16* __restrict__ A, long long sAp,
              const bf16* __restrict__ B, long long sBp,
              float* __restrict__ Cf, bf16* __restrict__ Cs, long long sCp,
              int M, int N, int K, int lda, int ldb, int ldc,
              long long sA, long long sB,
              int zdiv, long long sC1, long long sC2,
              float alpha, const float* __restrict__ bias, int relu)
{
    extern __shared__ __align__(16) char dynsmem[];
    const uint32_t sBase = (uint32_t)__cvta_generic_to_shared(dynsmem);

    const int bz = blockIdx.z;
    A += (long long)bz * sA;
    B += (long long)bz * sB;
    const long long cOff = (long long)(bz / zdiv) * sC1 + (long long)(bz % zdiv) * sC2;

    const int mBase = blockIdx.y * BM;
    const int nBase = blockIdx.x * BN;
    const int tid   = threadIdx.x;
    const int lane  = tid & 31;
    const int warp  = tid >> 5;
    const int wm    = warp >> 2;
    const int wn    = warp & 3;

    const int aRow  = (lane & 7) | (((lane >> 3) & 1) << 3);
    const int aK    = (lane >> 4) << 3;
    const int blane = lane & 15;

    constexpr int BPL_BYTES  = TB ? BPL_TB  : BPL_KM;
    constexpr int BBUF_BYTES = TB ? BBUF_TB : BBUF_KM;

    float acc[4][4][4];
    #pragma unroll
    for (int i = 0; i < 4; i++)
        #pragma unroll
        for (int j = 0; j < 4; j++)
            #pragma unroll
            for (int e = 0; e < 4; e++) acc[i][j][e] = 0.0f;

    const int nk = K >> 5;

    // tile loader: k-tile kt into buffer buf
    auto load_tile = [&](int kt, int buf) {
        const int k0 = kt << 5;
        // A: 2 planes x 128 rows x 32 halves (4 chunks/row)
        #pragma unroll
        for (int it = 0; it < 4; it++) {
            int idx = tid + it * 256;
            int pl  = idx >> 9;
            int rem = idx & 511;
            int r   = rem >> 2;
            int c   = (rem & 3) << 3;
            const bf16* src = A + (long long)pl * sAp + (long long)(mBase + r) * lda + k0 + c;
            uint32_t dst = sBase + buf * ABUF_B + pl * APL_B + (r * 40 + c) * 2;
            cp16(dst, src);
        }
        if (TB) {
            // B n-major: 2 planes x 128 rows x 32 halves
            #pragma unroll
            for (int it = 0; it < 4; it++) {
                int idx = tid + it * 256;
                int pl  = idx >> 9;
                int rem = idx & 511;
                int r   = rem >> 2;
                int c   = (rem & 3) << 3;
                const bf16* src = B + (long long)pl * sBp + (long long)(nBase + r) * ldb + k0 + c;
                uint32_t dst = sBase + BOFF_B + buf * BBUF_BYTES + pl * BPL_BYTES + (r * 40 + c) * 2;
                cp16(dst, src);
            }
        } else {
            // B k-major: 2 planes x 32 rows x 128 halves (16 chunks/row)
            #pragma unroll
            for (int it = 0; it < 4; it++) {
                int idx = tid + it * 256;
                int pl  = idx >> 9;
                int rem = idx & 511;
                int r   = rem >> 4;
                int c   = (rem & 15) << 3;
                int gn  = nBase + c;
                uint32_t dst = sBase + BOFF_B + buf * BBUF_BYTES + pl * BPL_BYTES + (r * 136 + c) * 2;
                if (gn < N) {
                    const bf16* src = B + (long long)pl * sBp + (long long)(k0 + r) * ldb + gn;
                    cp16(dst, src);
                } else {
                    cp16z(dst, B);
                }
            }
        }
        asm volatile("cp.async.commit_group;");
    };

    load_tile(0, 0);

    for (int kt = 0; kt < nk; kt++) {
        const bool more = (kt + 1 < nk);
        if (more) load_tile(kt + 1, (kt + 1) & 1);
        if (more) asm volatile("cp.async.wait_group 1;");
        else      asm volatile("cp.async.wait_group 0;");
        __syncthreads();

        const int buf = kt & 1;
        const uint32_t aB = sBase + buf * ABUF_B;
        const uint32_t bB = sBase + BOFF_B + buf * BBUF_BYTES;

        #pragma unroll
        for (int ks = 0; ks < 2; ks++) {
            uint32_t bh[4][2], blo[4][2];
            #pragma unroll
            for (int ni = 0; ni < 4; ni++) {
                if (TB) {
                    int off = (wn * 32 + ni * 8 + (blane & 7)) * 40
                            + ks * 16 + ((blane >> 3) << 3);
                    uint32_t ad = bB + off * 2;
                    ldsm2(bh[ni], ad);
                    ldsm2(blo[ni], ad + BPL_BYTES);
                } else {
                    int off = (ks * 16 + blane) * 136 + wn * 32 + ni * 8;
                    uint32_t ad = bB + off * 2;
                    ldsm2t(bh[ni], ad);
                    ldsm2t(blo[ni], ad + BPL_BYTES);
                }
            }
            #pragma unroll
            for (int mi = 0; mi < 4; mi++) {
                uint32_t ah[4], al[4];
                int off = (wm * 64 + mi * 16 + aRow) * 40 + ks * 16 + aK;
                uint32_t ad = aB + off * 2;
                ldsm4(ah, ad);
                ldsm4(al, ad + APL_B);
                #pragma unroll
                for (int ni = 0; ni < 4; ni++) {
                    mma16816(acc[mi][ni], ah, bh[ni]);   // hi*hi
                    mma16816(acc[mi][ni], ah, blo[ni]);  // hi*lo
                    mma16816(acc[mi][ni], al, bh[ni]);   // lo*hi
                }
            }
        }
        __syncthreads();
    }

    // ---- epilogue ----
    const int g   = lane >> 2;
    const int tig = lane & 3;
    #pragma unroll
    for (int mi = 0; mi < 4; mi++) {
        #pragma unroll
        for (int ni = 0; ni < 4; ni++) {
            int n = nBase + wn * 32 + ni * 8 + tig * 2;
            if (n < N) {
                float bx = 0.f, by = 0.f;
                if (bias) { bx = bias[n]; by = bias[n + 1]; }
                #pragma unroll
                for (int rr = 0; rr < 2; rr++) {
                    int m = mBase + wm * 64 + mi * 16 + g + rr * 8;
                    float ox = acc[mi][ni][rr * 2 + 0] * alpha + bx;
                    float oy = acc[mi][ni][rr * 2 + 1] * alpha + by;
                    if (relu) { ox = fmaxf(ox, 0.f); oy = fmaxf(oy, 0.f); }
                    long long co = cOff + (long long)m * ldc + n;
                    if (Cf) *(float2*)(Cf + co) = make_float2(ox, oy);
                    if (Cs) {
                        bf16 hx, lx, hy, ly;
                        split2(ox, hx, lx); split2(oy, hy, ly);
                        *(bf162*)(Cs + co)       = bf162(hx, hy);
                        *(bf162*)(Cs + sCp + co) = bf162(lx, ly);
                    }
                }
            }
        }
    }
}

// fp32 -> bf16 hi/lo planes
__global__ __launch_bounds__(256)
void split_kernel(const float4* __restrict__ src, bf16* __restrict__ dst,
                  long long plane, int n4)
{
    int i = blockIdx.x * 256 + threadIdx.x;
    if (i < n4) {
        float4 v = src[i];
        bf16 h0, l0, h1, l1, h2, l2, h3, l3;
        split2(v.x, h0, l0); split2(v.y, h1, l1);
        split2(v.z, h2, l2); split2(v.w, h3, l3);
        bf162* dh = (bf162*)(dst + (long long)i * 4);
        dh[0] = bf162(h0, h1); dh[1] = bf162(h2, h3);
        bf162* dl = (bf162*)(dst + plane + (long long)i * 4);
        dl[0] = bf162(l0, l1); dl[1] = bf162(l2, l3);
    }
}

// row softmax (len 1024), fp32 in, bf16 hi/lo planes out
__global__ __launch_bounds__(256)
void softmax1024(const float* __restrict__ S, bf16* __restrict__ P, long long sPp)
{
    __shared__ float red[8];
    const long long rb = (long long)blockIdx.x * 1024;
    const int tid = threadIdx.x;

    float4 v = ((const float4*)(S + rb))[tid];
    float m = fmaxf(fmaxf(v.x, v.y), fmaxf(v.z, v.w));
    #pragma unroll
    for (int o = 16; o > 0; o >>= 1) m = fmaxf(m, __shfl_xor_sync(0xffffffffu, m, o));
    if ((tid & 31) == 0) red[tid >> 5] = m;
    __syncthreads();
    m = fmaxf(fmaxf(fmaxf(red[0], red[1]), fmaxf(red[2], red[3])),
              fmaxf(fmaxf(red[4], red[5]), fmaxf(red[6], red[7])));
    __syncthreads();

    v.x = __expf(v.x - m); v.y = __expf(v.y - m);
    v.z = __expf(v.z - m); v.w = __expf(v.w - m);
    float s = (v.x + v.y) + (v.z + v.w);
    #pragma unroll
    for (int o = 16; o > 0; o >>= 1) s += __shfl_xor_sync(0xffffffffu, s, o);
    if ((tid & 31) == 0) red[tid >> 5] = s;
    __syncthreads();
    s = ((red[0] + red[1]) + (red[2] + red[3])) + ((red[4] + red[5]) + (red[6] + red[7]));

    const float inv = 1.0f / s;
    v.x *= inv; v.y *= inv; v.z *= inv; v.w *= inv;

    bf16 h0, l0, h1, l1, h2, l2, h3, l3;
    split2(v.x, h0, l0); split2(v.y, h1, l1);
    split2(v.z, h2, l2); split2(v.w, h3, l3);
    bf162* ph = (bf162*)(P + rb + tid * 4);
    ph[0] = bf162(h0, h1); ph[1] = bf162(h2, h3);
    bf162* pl = (bf162*)(P + sPp + rb + tid * 4);
    pl[0] = bf162(l0, l1); pl[1] = bf162(l2, l3);
}

// O = LayerNorm(X + Y); optionally also write bf16 hi/lo planes Sout
__global__ __launch_bounds__(128)
void add_ln512(const float* __restrict__ X, const float* __restrict__ Y,
               const float* __restrict__ gamma, const float* __restrict__ beta,
               float* __restrict__ O, bf16* __restrict__ Sout, long long sSp)
{
    __shared__ float red[4];
    const long long row = blockIdx.x;
    const int tid = threadIdx.x;

    const float4 x4 = ((const float4*)(X + row * 512))[tid];
    const float4 y4 = ((const float4*)(Y + row * 512))[tid];
    float4 v;
    v.x = x4.x + y4.x; v.y = x4.y + y4.y; v.z = x4.z + y4.z; v.w = x4.w + y4.w;

    float s = (v.x + v.y) + (v.z + v.w);
    #pragma unroll
    for (int o = 16; o > 0; o >>= 1) s += __shfl_xor_sync(0xffffffffu, s, o);
    if ((tid & 31) == 0) red[tid >> 5] = s;
    __syncthreads();
    const float mean = ((red[0] + red[1]) + (red[2] + red[3])) * (1.0f / 512.0f);
    __syncthreads();

    float q = v.x * v.x + v.y * v.y + v.z * v.z + v.w * v.w;
    #pragma unroll
    for (int o = 16; o > 0; o >>= 1) q += __shfl_xor_sync(0xffffffffu, q, o);
    if ((tid & 31) == 0) red[tid >> 5] = q;
    __syncthreads();
    const float var = ((red[0] + red[1]) + (red[2] + red[3])) * (1.0f / 512.0f) - mean * mean;
    const float inv = rsqrtf(var + 1e-3f);

    const int n = tid * 4;
    const float4 g4 = *(const float4*)(gamma + n);
    const float4 b4 = *(const float4*)(beta + n);
    float4 o;
    o.x = g4.x * (v.x - mean) * inv + b4.x;
    o.y = g4.y * (v.y - mean) * inv + b4.y;
    o.z = g4.z * (v.z - mean) * inv + b4.z;
    o.w = g4.w * (v.w - mean) * inv + b4.w;
    ((float4*)(O + row * 512))[tid] = o;

    if (Sout) {
        bf16 h0, l0, h1, l1, h2, l2, h3, l3;
        split2(o.x, h0, l0); split2(o.y, h1, l1);
        split2(o.z, h2, l2); split2(o.w, h3, l3);
        bf162* dh = (bf162*)(Sout + row * 512 + n);
        dh[0] = bf162(h0, h1); dh[1] = bf162(h2, h3);
        bf162* dl = (bf162*)(Sout + sSp + row * 512 + n);
        dl[0] = bf162(l0, l1); dl[1] = bf162(l2, l3);
    }
}

// ---------------------------------------------------------------------------

static void run_gemm(bool tb, const bf16* A, long long sAp, const bf16* B, long long sBp,
                     float* Cf, bf16* Cs, long long sCp,
                     int M, int N, int K, int lda, int ldb, int ldc,
                     long long sA, long long sB, int zdiv, long long sC1, long long sC2,
                     int batch, float alpha, const float* bias, int relu)
{
    dim3 grid((N + BN - 1) / BN, M / BM, batch);
    if (tb)
        mma_gemm<true><<<grid, 256, SMEM_BYTES>>>(A, sAp, B, sBp, Cf, Cs, sCp,
            M, N, K, lda, ldb, ldc, sA, sB, zdiv, sC1, sC2, alpha, bias, relu);
    else
        mma_gemm<false><<<grid, 256, SMEM_BYTES>>>(A, sAp, B, sBp, Cf, Cs, sCp,
            M, N, K, lda, ldb, ldc, sA, sB, zdiv, sC1, sC2, alpha, bias, relu);
}

static void run_split(const float* src, bf16* dst, long long plane, long long n)
{
    int n4 = (int)(n / 4);
    split_kernel<<<(n4 + 255) / 256, 256>>>((const float4*)src, dst, plane, n4);
}

struct Ptrs {
    float *sc, *mha, *h, *f2;
    bf16 *xs, *qws, *kws, *vws, *lws, *w1s, *w2s;
    bf16 *qs, *ks, *vs, *ps, *ats, *hs, *f1s;
};

static Ptrs get_ptrs()
{
    static Ptrs p;
    static bool init = false;
    if (!init) {
        cudaGetSymbolAddress((void**)&p.sc,  g_sc);
        cudaGetSymbolAddress((void**)&p.mha, g_mha);
        cudaGetSymbolAddress((void**)&p.h,   g_h);
        cudaGetSymbolAddress((void**)&p.f2,  g_f2);
        cudaGetSymbolAddress((void**)&p.xs,  g_xs);
        cudaGetSymbolAddress((void**)&p.qws, g_qws);
        cudaGetSymbolAddress((void**)&p.kws, g_kws);
        cudaGetSymbolAddress((void**)&p.vws, g_vws);
        cudaGetSymbolAddress((void**)&p.lws, g_lws);
        cudaGetSymbolAddress((void**)&p.w1s, g_w1s);
        cudaGetSymbolAddress((void**)&p.w2s, g_w2s);
        cudaGetSymbolAddress((void**)&p.qs,  g_qs);
        cudaGetSymbolAddress((void**)&p.ks,  g_ks);
        cudaGetSymbolAddress((void**)&p.vs,  g_vs);
        cudaGetSymbolAddress((void**)&p.ps,  g_ps);
        cudaGetSymbolAddress((void**)&p.ats, g_ats);
        cudaGetSymbolAddress((void**)&p.hs,  g_hs);
        cudaGetSymbolAddress((void**)&p.f1s, g_f1s);
        cudaFuncSetAttribute(mma_gemm<true>,  cudaFuncAttributeMaxDynamicSharedMemorySize, SMEM_BYTES);
        cudaFuncSetAttribute(mma_gemm<false>, cudaFuncAttributeMaxDynamicSharedMemorySize, SMEM_BYTES);
        init = true;
    }
    return p;
}

extern "C" void kernel_launch(void* const* d_in, const int* in_sizes, int n_in,
                              void* d_out, int out_size)
{
    const float* x      = (const float*)d_in[0];   // [8,1024,512]
    const float* qw     = (const float*)d_in[1];   // [8,512,64]
    const float* kw     = (const float*)d_in[2];   // [8,512,64]
    const float* vw     = (const float*)d_in[3];   // [8,512,512]
    const float* lw     = (const float*)d_in[4];   // [4096,512]
    const float* gamma1 = (const float*)d_in[5];
    const float* beta1  = (const float*)d_in[6];
    const float* w1     = (const float*)d_in[7];   // [512,2048]
    const float* b1     = (const float*)d_in[8];
    const float* w2     = (const float*)d_in[9];   // [2048,512]
    const float* b2     = (const float*)d_in[10];
    const float* gamma2 = (const float*)d_in[11];
    const float* beta2  = (const float*)d_in[12];
    float* out = (float*)d_out;

    Ptrs p = get_ptrs();

    const int M = 8192;
    const float scale = 0.044194173824159216f;  // 1/sqrt(512)

    // input/weight splits
    run_split(x,  p.xs,  4194304, 4194304);
    run_split(qw, p.qws, 262144,  262144);
    run_split(kw, p.kws, 262144,  262144);
    run_split(vw, p.vws, 2097152, 2097152);
    run_split(lw, p.lws, 2097152, 2097152);
    run_split(w1, p.w1s, 1048576, 1048576);
    run_split(w2, p.w2s, 1048576, 1048576);

    // Q = x @ qw[h] -> split planes  [H][8192][64]
    run_gemm(false, p.xs, 4194304, p.qws, 262144, nullptr, p.qs, 4194304,
             M, 64, 512, 512, 64, 64, 0LL, 32768LL, 1, 524288LL, 0LL, 8, 1.0f, nullptr, 0);
    // K = x @ kw[h]
    run_gemm(false, p.xs, 4194304, p.kws, 262144, nullptr, p.ks, 4194304,
             M, 64, 512, 512, 64, 64, 0LL, 32768LL, 1, 524288LL, 0LL, 8, 1.0f, nullptr, 0);
    // V = x @ vw[h] -> split planes [H][8192][512]
    run_gemm(false, p.xs, 4194304, p.vws, 2097152, nullptr, p.vs, 33554432,
             M, 512, 512, 512, 512, 512, 0LL, 262144LL, 1, 4194304LL, 0LL, 8, 1.0f, nullptr, 0);

    // scores[z] = scale * Q_z @ K_z^T  (fp32 out)
    run_gemm(true, p.qs, 4194304, p.ks, 4194304, p.sc, nullptr, 0LL,
             1024, 1024, 64, 64, 64, 1024, 65536LL, 65536LL, 1, 1048576LL, 0LL,
             64, scale, nullptr, 0);

    // softmax -> prob split planes
    softmax1024<<<65536, 256>>>(p.sc, p.ps, 67108864LL);

    // attn[z] = P_z @ V_z -> split planes into concat layout [8192][4096]
    run_gemm(false, p.ps, 67108864, p.vs, 33554432, nullptr, p.ats, 33554432,
             1024, 512, 1024, 1024, 512, 4096, 1048576LL, 524288LL, 8, 512LL, 4194304LL,
             64, 1.0f, nullptr, 0);

    // mha = attn @ lw (fp32 out)
    run_gemm(false, p.ats, 33554432, p.lws, 2097152, p.mha, nullptr, 0LL,
             M, 512, 4096, 4096, 512, 512, 0LL, 0LL, 1, 0LL, 0LL, 1, 1.0f, nullptr, 0);

    // h = LN(x + mha)  (fp32 + split planes)
    add_ln512<<<8192, 128>>>(x, p.mha, gamma1, beta1, p.h, p.hs, 4194304LL);

    // f1 = relu(h @ w1 + b1) -> split planes
    run_gemm(false, p.hs, 4194304, p.w1s, 1048576, nullptr, p.f1s, 16777216,
             M, 2048, 512, 512, 2048, 2048, 0LL, 0LL, 1, 0LL, 0LL, 1, 1.0f, b1, 1);

    // f2 = f1 @ w2 + b2 (fp32 out)
    run_gemm(false, p.f1s, 16777216, p.w2s, 1048576, p.f2, nullptr, 0LL,
             M, 512, 2048, 2048, 512, 512, 0LL, 0LL, 1, 0LL, 0LL, 1, 1.0f, b2, 0);

    // out = LN(h + f2)
    add_ln512<<<8192, 128>>>(p.h, p.f2, gamma2, beta2, out, nullptr, 0LL);
}

// round 8
// speedup vs baseline: 3.3186x; 1.2304x over previous
#include <cuda_runtime.h>
#include <cstdint>

// ---------------- scratch (device globals; no allocation allowed) -----------
__device__ float g_q [4194304];    // [H][8192][64]
__device__ float g_k [4194304];    // [H][8192][64]
__device__ float g_v [33554432];   // [H][8192][512]
__device__ float g_sc[67108864];   // [64][1024][1024] scores/probs (in-place)
__device__ float g_at[33554432];   // [8192][4096] concat heads
__device__ float g_mha[4194304];
__device__ float g_h [4194304];
__device__ float g_f1[16777216];   // [8192][2048]
__device__ float g_f2[4194304];

#define BM 128
#define BN 128
#define BK 32
#define ASTRF   36       // A smem row stride (floats): conflict-free
#define BSTRF_KM 136     // B smem row stride, k-major (floats)
#define A_BYTES 18432    // 128*36*4
#define STAGE   36864    // A + B region per stage
#define SMEM_BYTES 73728

__device__ __forceinline__ void cp16(uint32_t dst, const void* src) {
    asm volatile("cp.async.cg.shared.global [%0], [%1], 16;" :: "r"(dst), "l"(src));
}
__device__ __forceinline__ void cp16z(uint32_t dst, const void* src) {
    asm volatile("cp.async.cg.shared.global [%0], [%1], 16, %2;"
                 :: "r"(dst), "l"(src), "r"(0));
}
__device__ __forceinline__ uint32_t f2tf(float f) {
    uint32_t r;
    asm("cvt.rna.tf32.f32 %0, %1;" : "=r"(r) : "f"(f));
    return r;
}
__device__ __forceinline__ void mma_tf32(float* c, const uint32_t* a, const uint32_t* b) {
    asm volatile(
        "mma.sync.aligned.m16n8k8.row.col.f32.tf32.tf32.f32 "
        "{%0,%1,%2,%3},{%4,%5,%6,%7},{%8,%9},{%0,%1,%2,%3};"
        : "+f"(c[0]), "+f"(c[1]), "+f"(c[2]), "+f"(c[3])
        : "r"(a[0]), "r"(a[1]), "r"(a[2]), "r"(a[3]), "r"(b[0]), "r"(b[1]));
}

// C[m,n] (+z offsets) = alpha * sum_k A[m,k] * (TB ? B[n,k] : B[k,n]) (+bias)(relu)
// fp32 in / fp32 out; tf32 tensor-core inner product.
// Requires M%128==0, K%32==0; N<BN handled by zero-fill + epilogue guard.
template<bool TB>
__global__ __launch_bounds__(256, 2)
void tf32_gemm(const float* __restrict__ A, const float* __restrict__ B,
               float* __restrict__ C, int M, int N, int K,
               int lda, int ldb, int ldc,
               long long sA, long long sB,
               int zdiv, long long sC1, long long sC2,
               float alpha, const float* __restrict__ bias, int relu)
{
    extern __shared__ __align__(16) char dsm[];
    const uint32_t sBase = (uint32_t)__cvta_generic_to_shared(dsm);

    const int bz = blockIdx.z;
    A += (long long)bz * sA;
    B += (long long)bz * sB;
    const long long cOff = (long long)(bz / zdiv) * sC1 + (long long)(bz % zdiv) * sC2;

    const int mBase = blockIdx.y * BM;
    const int nBase = blockIdx.x * BN;
    const int tid   = threadIdx.x;
    const int lane  = tid & 31;
    const int warp  = tid >> 5;
    const int wm    = warp >> 2;     // 0..1 -> 64 rows
    const int wn    = warp & 3;      // 0..3 -> 32 cols

    const int g   = lane >> 2;       // group id (row within 8)
    const int tg  = lane & 3;        // thread in group (k / col pair)

    float acc[4][4][4];
    #pragma unroll
    for (int i = 0; i < 4; i++)
        #pragma unroll
        for (int j = 0; j < 4; j++)
            #pragma unroll
            for (int e = 0; e < 4; e++) acc[i][j][e] = 0.0f;

    const int nk = K >> 5;

    auto load_tile = [&](int kt, int buf) {
        const int k0 = kt << 5;
        const uint32_t sb = sBase + buf * STAGE;
        // A: 128 rows x 32 floats, 8 chunks(16B)/row -> 1024 chunks
        #pragma unroll
        for (int it = 0; it < 4; it++) {
            int idx = tid + it * 256;
            int r = idx >> 3, c = idx & 7;
            cp16(sb + r * 144 + c * 16,
                 A + (long long)(mBase + r) * lda + k0 + c * 4);
        }
        if (TB) {
            // B n-major: 128 rows x 32 floats
            #pragma unroll
            for (int it = 0; it < 4; it++) {
                int idx = tid + it * 256;
                int r = idx >> 3, c = idx & 7;
                int gn = nBase + r;
                uint32_t dst = sb + A_BYTES + r * 144 + c * 16;
                if (gn < N) cp16(dst, B + (long long)gn * ldb + k0 + c * 4);
                else        cp16z(dst, B);
            }
        } else {
            // B k-major: 32 rows x 128 floats, 32 chunks/row
            #pragma unroll
            for (int it = 0; it < 4; it++) {
                int idx = tid + it * 256;
                int r = idx >> 5, cc = idx & 31;
                int gn = nBase + cc * 4;
                uint32_t dst = sb + A_BYTES + r * 544 + cc * 16;
                if (gn < N) cp16(dst, B + (long long)(k0 + r) * ldb + gn);
                else        cp16z(dst, B);
            }
        }
        asm volatile("cp.async.commit_group;" ::: "memory");
    };

    load_tile(0, 0);

    for (int kt = 0; kt < nk; kt++) {
        if (kt + 1 < nk) {
            load_tile(kt + 1, (kt + 1) & 1);
            asm volatile("cp.async.wait_group 1;" ::: "memory");
        } else {
            asm volatile("cp.async.wait_group 0;" ::: "memory");
        }
        __syncthreads();

        const int buf = kt & 1;
        const float* As = (const float*)(dsm + buf * STAGE);
        const float* Bs = (const float*)(dsm + buf * STAGE + A_BYTES);

        #pragma unroll
        for (int ks = 0; ks < 4; ks++) {
            uint32_t bfr[4][2];
            #pragma unroll
            for (int ni = 0; ni < 4; ni++) {
                if (TB) {
                    int base = (wn * 32 + ni * 8 + g) * ASTRF + ks * 8 + tg;
                    bfr[ni][0] = f2tf(Bs[base]);
                    bfr[ni][1] = f2tf(Bs[base + 4]);
                } else {
                    int base = (ks * 8 + tg) * BSTRF_KM + wn * 32 + ni * 8 + g;
                    bfr[ni][0] = f2tf(Bs[base]);
                    bfr[ni][1] = f2tf(Bs[base + 4 * BSTRF_KM]);
                }
            }
            #pragma unroll
            for (int mi = 0; mi < 4; mi++) {
                int ab = (wm * 64 + mi * 16 + g) * ASTRF + ks * 8 + tg;
                uint32_t af[4];
                af[0] = f2tf(As[ab]);
                af[1] = f2tf(As[ab + 8 * ASTRF]);
                af[2] = f2tf(As[ab + 4]);
                af[3] = f2tf(As[ab + 8 * ASTRF + 4]);
                #pragma unroll
                for (int ni = 0; ni < 4; ni++)
                    mma_tf32(acc[mi][ni], af, bfr[ni]);
            }
        }
        __syncthreads();
    }

    // ---- epilogue ----
    #pragma unroll
    for (int mi = 0; mi < 4; mi++) {
        #pragma unroll
        for (int ni = 0; ni < 4; ni++) {
            int n = nBase + wn * 32 + ni * 8 + tg * 2;
            if (n < N) {
                float bx = 0.f, by = 0.f;
                if (bias) { bx = bias[n]; by = bias[n + 1]; }
                #pragma unroll
                for (int rr = 0; rr < 2; rr++) {
                    int m = mBase + wm * 64 + mi * 16 + g + rr * 8;
                    float ox = acc[mi][ni][rr * 2 + 0] * alpha + bx;
                    float oy = acc[mi][ni][rr * 2 + 1] * alpha + by;
                    if (relu) { ox = fmaxf(ox, 0.f); oy = fmaxf(oy, 0.f); }
                    *(float2*)(C + cOff + (long long)m * ldc + n) = make_float2(ox, oy);
                }
            }
        }
    }
}

// row softmax over rows of length 1024; one block (256 thr) per row, in place
__global__ __launch_bounds__(256)
void softmax1024(float* __restrict__ S)
{
    __shared__ float red[8];
    float* p = S + (long long)blockIdx.x * 1024;
    const int tid = threadIdx.x;

    float4 v = reinterpret_cast<float4*>(p)[tid];
    float m = fmaxf(fmaxf(v.x, v.y), fmaxf(v.z, v.w));
    #pragma unroll
    for (int o = 16; o > 0; o >>= 1) m = fmaxf(m, __shfl_xor_sync(0xffffffffu, m, o));
    if ((tid & 31) == 0) red[tid >> 5] = m;
    __syncthreads();
    m = fmaxf(fmaxf(fmaxf(red[0], red[1]), fmaxf(red[2], red[3])),
              fmaxf(fmaxf(red[4], red[5]), fmaxf(red[6], red[7])));
    __syncthreads();

    v.x = __expf(v.x - m); v.y = __expf(v.y - m);
    v.z = __expf(v.z - m); v.w = __expf(v.w - m);
    float s = (v.x + v.y) + (v.z + v.w);
    #pragma unroll
    for (int o = 16; o > 0; o >>= 1) s += __shfl_xor_sync(0xffffffffu, s, o);
    if ((tid & 31) == 0) red[tid >> 5] = s;
    __syncthreads();
    s = ((red[0] + red[1]) + (red[2] + red[3])) + ((red[4] + red[5]) + (red[6] + red[7]));

    const float inv = 1.0f / s;
    v.x *= inv; v.y *= inv; v.z *= inv; v.w *= inv;
    reinterpret_cast<float4*>(p)[tid] = v;
}

// O = LayerNorm(X + Y); rows of 512
__global__ __launch_bounds__(128)
void add_ln512(const float* __restrict__ X, const float* __restrict__ Y,
               const float* __restrict__ gamma, const float* __restrict__ beta,
               float* __restrict__ O)
{
    __shared__ float red[4];
    const long long row = blockIdx.x;
    const int tid = threadIdx.x;

    const float4 x4 = ((const float4*)(X + row * 512))[tid];
    const float4 y4 = ((const float4*)(Y + row * 512))[tid];
    float4 v;
    v.x = x4.x + y4.x; v.y = x4.y + y4.y; v.z = x4.z + y4.z; v.w = x4.w + y4.w;

    float s = (v.x + v.y) + (v.z + v.w);
    #pragma unroll
    for (int o = 16; o > 0; o >>= 1) s += __shfl_xor_sync(0xffffffffu, s, o);
    if ((tid & 31) == 0) red[tid >> 5] = s;
    __syncthreads();
    const float mean = ((red[0] + red[1]) + (red[2] + red[3])) * (1.0f / 512.0f);
    __syncthreads();

    float q = v.x * v.x + v.y * v.y + v.z * v.z + v.w * v.w;
    #pragma unroll
    for (int o = 16; o > 0; o >>= 1) q += __shfl_xor_sync(0xffffffffu, q, o);
    if ((tid & 31) == 0) red[tid >> 5] = q;
    __syncthreads();
    const float var = ((red[0] + red[1]) + (red[2] + red[3])) * (1.0f / 512.0f) - mean * mean;
    const float inv = rsqrtf(var + 1e-3f);

    const int n = tid * 4;
    const float4 g4 = *(const float4*)(gamma + n);
    const float4 b4 = *(const float4*)(beta + n);
    float4 o;
    o.x = g4.x * (v.x - mean) * inv + b4.x;
    o.y = g4.y * (v.y - mean) * inv + b4.y;
    o.z = g4.z * (v.z - mean) * inv + b4.z;
    o.w = g4.w * (v.w - mean) * inv + b4.w;
    ((float4*)(O + row * 512))[tid] = o;
}

// ---------------------------------------------------------------------------

static void run_gemm(bool tb, const float* A, const float* B, float* C,
                     int M, int N, int K, int lda, int ldb, int ldc,
                     long long sA, long long sB,
                     int zdiv, long long sC1, long long sC2,
                     int batch, float alpha, const float* bias, int relu)
{
    dim3 grid((N + BN - 1) / BN, M / BM, batch);
    if (tb)
        tf32_gemm<true><<<grid, 256, SMEM_BYTES>>>(A, B, C, M, N, K, lda, ldb, ldc,
            sA, sB, zdiv, sC1, sC2, alpha, bias, relu);
    else
        tf32_gemm<false><<<grid, 256, SMEM_BYTES>>>(A, B, C, M, N, K, lda, ldb, ldc,
            sA, sB, zdiv, sC1, sC2, alpha, bias, relu);
}

struct Ptrs {
    float *q, *k, *v, *sc, *at, *mha, *h, *f1, *f2;
};

static Ptrs get_ptrs()
{
    static Ptrs p;
    static bool init = false;
    if (!init) {
        cudaGetSymbolAddress((void**)&p.q,   g_q);
        cudaGetSymbolAddress((void**)&p.k,   g_k);
        cudaGetSymbolAddress((void**)&p.v,   g_v);
        cudaGetSymbolAddress((void**)&p.sc,  g_sc);
        cudaGetSymbolAddress((void**)&p.at,  g_at);
        cudaGetSymbolAddress((void**)&p.mha, g_mha);
        cudaGetSymbolAddress((void**)&p.h,   g_h);
        cudaGetSymbolAddress((void**)&p.f1,  g_f1);
        cudaGetSymbolAddress((void**)&p.f2,  g_f2);
        cudaFuncSetAttribute(tf32_gemm<true>,  cudaFuncAttributeMaxDynamicSharedMemorySize, SMEM_BYTES);
        cudaFuncSetAttribute(tf32_gemm<false>, cudaFuncAttributeMaxDynamicSharedMemorySize, SMEM_BYTES);
        init = true;
    }
    return p;
}

extern "C" void kernel_launch(void* const* d_in, const int* in_sizes, int n_in,
                              void* d_out, int out_size)
{
    const float* x      = (const float*)d_in[0];   // [8,1024,512]
    const float* qw     = (const float*)d_in[1];   // [8,512,64]
    const float* kw     = (const float*)d_in[2];   // [8,512,64]
    const float* vw     = (const float*)d_in[3];   // [8,512,512]
    const float* lw     = (const float*)d_in[4];   // [4096,512]
    const float* gamma1 = (const float*)d_in[5];
    const float* beta1  = (const float*)d_in[6];
    const float* w1     = (const float*)d_in[7];   // [512,2048]
    const float* b1     = (const float*)d_in[8];
    const float* w2     = (const float*)d_in[9];   // [2048,512]
    const float* b2     = (const float*)d_in[10];
    const float* gamma2 = (const float*)d_in[11];
    const float* beta2  = (const float*)d_in[12];
    float* out = (float*)d_out;

    Ptrs p = get_ptrs();
    const int M = 8192;
    const float scale = 0.044194173824159216f;  // 1/sqrt(512)

    // Q = x @ qw[h]  -> [H][8192][64]
    run_gemm(false, x, qw, p.q, M, 64, 512, 512, 64, 64,
             0LL, 32768LL, 1, 524288LL, 0LL, 8, 1.0f, nullptr, 0);
    // K = x @ kw[h]
    run_gemm(false, x, kw, p.k, M, 64, 512, 512, 64, 64,
             0LL, 32768LL, 1, 524288LL, 0LL, 8, 1.0f, nullptr, 0);
    // V = x @ vw[h] -> [H][8192][512]
    run_gemm(false, x, vw, p.v, M, 512, 512, 512, 512, 512,
             0LL, 262144LL, 1, 4194304LL, 0LL, 8, 1.0f, nullptr, 0);

    // scores[z=h*8+b] = scale * Q_z @ K_z^T  (1024x1024, K=64)
    run_gemm(true, p.q, p.k, p.sc, 1024, 1024, 64, 64, 64, 1024,
             65536LL, 65536LL, 1, 1048576LL, 0LL, 64, scale, nullptr, 0);

    softmax1024<<<65536, 256>>>(p.sc);

    // attn[z] = P_z @ V_z -> concat layout [8192][4096]
    run_gemm(false, p.sc, p.v, p.at, 1024, 512, 1024, 1024, 512, 4096,
             1048576LL, 524288LL, 8, 512LL, 4194304LL, 64, 1.0f, nullptr, 0);

    // mha = attn @ lw
    run_gemm(false, p.at, lw, p.mha, M, 512, 4096, 4096, 512, 512,
             0LL, 0LL, 1, 0LL, 0LL, 1, 1.0f, nullptr, 0);

    // h = LN(x + mha)
    add_ln512<<<8192, 128>>>(x, p.mha, gamma1, beta1, p.h);

    // f1 = relu(h @ w1 + b1)
    run_gemm(false, p.h, w1, p.f1, M, 2048, 512, 512, 2048, 2048,
             0LL, 0LL, 1, 0LL, 0LL, 1, 1.0f, b1, 1);
    // f2 = f1 @ w2 + b2
    run_gemm(false, p.f1, w2, p.f2, M, 512, 2048, 2048, 512, 512,
             0LL, 0LL, 1, 0LL, 0LL, 1, 1.0f, b2, 0);

    // out = LN(h + f2)
    add_ln512<<<8192, 128>>>(p.h, p.f2, gamma2, beta2, out);
}

// round 9
// speedup vs baseline: 3.3793x; 1.0183x over previous
#include <cuda_runtime.h>
#include <cstdint>

// ---------------- scratch (device globals; no allocation allowed) -----------
__device__ float g_q [4194304];    // [H][8192][64]
__device__ float g_k [4194304];    // [H][8192][64]
__device__ float g_v [33554432];   // [H][8192][512]
__device__ float g_sc[67108864];   // [64][1024][1024] scores/probs (in-place)
__device__ float g_at[33554432];   // [8192][4096] concat heads
__device__ float g_mha[4194304];
__device__ float g_h [4194304];
__device__ float g_f1[16777216];   // [8192][2048]
__device__ float g_f2[4194304];
// tf32-rounded copies of raw inputs
__device__ float g_xr [4194304];
__device__ float g_qwr[262144];
__device__ float g_kwr[262144];
__device__ float g_vwr[2097152];
__device__ float g_lwr[2097152];
__device__ float g_w1r[1048576];
__device__ float g_w2r[1048576];

#define BM 128
#define BN 128
#define BK 32
#define ASTRF   36       // A smem row stride (floats): conflict-free
#define BSTRF_KM 136     // B smem row stride, k-major (floats)
#define A_BYTES 18432    // 128*36*4
#define STAGE   36864
#define SMEM_BYTES 73728

__device__ __forceinline__ void cp16(uint32_t dst, const void* src) {
    asm volatile("cp.async.cg.shared.global [%0], [%1], 16;" :: "r"(dst), "l"(src));
}
__device__ __forceinline__ void cp16z(uint32_t dst, const void* src) {
    asm volatile("cp.async.cg.shared.global [%0], [%1], 16, %2;"
                 :: "r"(dst), "l"(src), "r"(0));
}
__device__ __forceinline__ float rnd_tf32(float f) {
    uint32_t r;
    asm("cvt.rna.tf32.f32 %0, %1;" : "=r"(r) : "f"(f));
    return __uint_as_float(r);
}
__device__ __forceinline__ void mma_tf32(float* c, const uint32_t* a, const uint32_t* b) {
    asm volatile(
        "mma.sync.aligned.m16n8k8.row.col.f32.tf32.tf32.f32 "
        "{%0,%1,%2,%3},{%4,%5,%6,%7},{%8,%9},{%0,%1,%2,%3};"
        : "+f"(c[0]), "+f"(c[1]), "+f"(c[2]), "+f"(c[3])
        : "r"(a[0]), "r"(a[1]), "r"(a[2]), "r"(a[3]), "r"(b[0]), "r"(b[1]));
}

// C[m,n] (+z offsets) = alpha * sum_k A[m,k] * (TB ? B[n,k] : B[k,n]) (+bias)(relu)
// All operands MUST already be tf32-rounded fp32; raw bits feed the MMA.
// roundOut: store tf32-rounded outputs (for values feeding later GEMMs).
template<bool TB>
__global__ __launch_bounds__(256, 2)
void tf32_gemm(const float* __restrict__ A, const float* __restrict__ B,
               float* __restrict__ C, int M, int N, int K,
               int lda, int ldb, int ldc,
               long long sA, long long sB,
               int zdiv, long long sC1, long long sC2,
               float alpha, const float* __restrict__ bias, int relu, int roundOut)
{
    extern __shared__ __align__(16) char dsm[];
    const uint32_t sBase = (uint32_t)__cvta_generic_to_shared(dsm);

    const int bz = blockIdx.z;
    A += (long long)bz * sA;
    B += (long long)bz * sB;
    const long long cOff = (long long)(bz / zdiv) * sC1 + (long long)(bz % zdiv) * sC2;

    const int mBase = blockIdx.y * BM;
    const int nBase = blockIdx.x * BN;
    const int tid   = threadIdx.x;
    const int lane  = tid & 31;
    const int warp  = tid >> 5;
    const int wm    = warp >> 2;
    const int wn    = warp & 3;
    const int g     = lane >> 2;
    const int tg    = lane & 3;

    float acc[4][4][4];
    #pragma unroll
    for (int i = 0; i < 4; i++)
        #pragma unroll
        for (int j = 0; j < 4; j++)
            #pragma unroll
            for (int e = 0; e < 4; e++) acc[i][j][e] = 0.0f;

    const int nk = K >> 5;

    auto load_tile = [&](int kt, int buf) {
        const int k0 = kt << 5;
        const uint32_t sb = sBase + buf * STAGE;
        #pragma unroll
        for (int it = 0; it < 4; it++) {
            int idx = tid + it * 256;
            int r = idx >> 3, c = idx & 7;
            cp16(sb + r * 144 + c * 16,
                 A + (long long)(mBase + r) * lda + k0 + c * 4);
        }
        if (TB) {
            #pragma unroll
            for (int it = 0; it < 4; it++) {
                int idx = tid + it * 256;
                int r = idx >> 3, c = idx & 7;
                int gn = nBase + r;
                uint32_t dst = sb + A_BYTES + r * 144 + c * 16;
                if (gn < N) cp16(dst, B + (long long)gn * ldb + k0 + c * 4);
                else        cp16z(dst, B);
            }
        } else {
            #pragma unroll
            for (int it = 0; it < 4; it++) {
                int idx = tid + it * 256;
                int r = idx >> 5, cc = idx & 31;
                int gn = nBase + cc * 4;
                uint32_t dst = sb + A_BYTES + r * 544 + cc * 16;
                if (gn < N) cp16(dst, B + (long long)(k0 + r) * ldb + gn);
                else        cp16z(dst, B);
            }
        }
        asm volatile("cp.async.commit_group;" ::: "memory");
    };

    load_tile(0, 0);

    for (int kt = 0; kt < nk; kt++) {
        if (kt + 1 < nk) {
            load_tile(kt + 1, (kt + 1) & 1);
            asm volatile("cp.async.wait_group 1;" ::: "memory");
        } else {
            asm volatile("cp.async.wait_group 0;" ::: "memory");
        }
        __syncthreads();

        const int buf = kt & 1;
        const uint32_t* As = (const uint32_t*)(dsm + buf * STAGE);
        const uint32_t* Bs = (const uint32_t*)(dsm + buf * STAGE + A_BYTES);

        #pragma unroll
        for (int ks = 0; ks < 4; ks++) {
            uint32_t bfr[4][2];
            #pragma unroll
            for (int ni = 0; ni < 4; ni++) {
                if (TB) {
                    int base = (wn * 32 + ni * 8 + g) * ASTRF + ks * 8 + tg;
                    bfr[ni][0] = Bs[base];
                    bfr[ni][1] = Bs[base + 4];
                } else {
                    int base = (ks * 8 + tg) * BSTRF_KM + wn * 32 + ni * 8 + g;
                    bfr[ni][0] = Bs[base];
                    bfr[ni][1] = Bs[base + 4 * BSTRF_KM];
                }
            }
            #pragma unroll
            for (int mi = 0; mi < 4; mi++) {
                int ab = (wm * 64 + mi * 16 + g) * ASTRF + ks * 8 + tg;
                uint32_t af[4];
                af[0] = As[ab];
                af[1] = As[ab + 8 * ASTRF];
                af[2] = As[ab + 4];
                af[3] = As[ab + 8 * ASTRF + 4];
                #pragma unroll
                for (int ni = 0; ni < 4; ni++)
                    mma_tf32(acc[mi][ni], af, bfr[ni]);
            }
        }
        __syncthreads();
    }

    // ---- epilogue ----
    #pragma unroll
    for (int mi = 0; mi < 4; mi++) {
        #pragma unroll
        for (int ni = 0; ni < 4; ni++) {
            int n = nBase + wn * 32 + ni * 8 + tg * 2;
            if (n < N) {
                float bx = 0.f, by = 0.f;
                if (bias) { bx = bias[n]; by = bias[n + 1]; }
                #pragma unroll
                for (int rr = 0; rr < 2; rr++) {
                    int m = mBase + wm * 64 + mi * 16 + g + rr * 8;
                    float ox = acc[mi][ni][rr * 2 + 0] * alpha + bx;
                    float oy = acc[mi][ni][rr * 2 + 1] * alpha + by;
                    if (relu) { ox = fmaxf(ox, 0.f); oy = fmaxf(oy, 0.f); }
                    if (roundOut) { ox = rnd_tf32(ox); oy = rnd_tf32(oy); }
                    *(float2*)(C + cOff + (long long)m * ldc + n) = make_float2(ox, oy);
                }
            }
        }
    }
}

// tf32-round copy
__global__ __launch_bounds__(256)
void round_copy(const float4* __restrict__ src, float4* __restrict__ dst, int n4)
{
    int i = blockIdx.x * 256 + threadIdx.x;
    if (i < n4) {
        float4 v = src[i];
        v.x = rnd_tf32(v.x); v.y = rnd_tf32(v.y);
        v.z = rnd_tf32(v.z); v.w = rnd_tf32(v.w);
        dst[i] = v;
    }
}

// row softmax (len 1024) in place; probs stored tf32-rounded
__global__ __launch_bounds__(256)
void softmax1024(float* __restrict__ S)
{
    __shared__ float red[8];
    float* p = S + (long long)blockIdx.x * 1024;
    const int tid = threadIdx.x;

    float4 v = reinterpret_cast<float4*>(p)[tid];
    float m = fmaxf(fmaxf(v.x, v.y), fmaxf(v.z, v.w));
    #pragma unroll
    for (int o = 16; o > 0; o >>= 1) m = fmaxf(m, __shfl_xor_sync(0xffffffffu, m, o));
    if ((tid & 31) == 0) red[tid >> 5] = m;
    __syncthreads();
    m = fmaxf(fmaxf(fmaxf(red[0], red[1]), fmaxf(red[2], red[3])),
              fmaxf(fmaxf(red[4], red[5]), fmaxf(red[6], red[7])));
    __syncthreads();

    v.x = __expf(v.x - m); v.y = __expf(v.y - m);
    v.z = __expf(v.z - m); v.w = __expf(v.w - m);
    float s = (v.x + v.y) + (v.z + v.w);
    #pragma unroll
    for (int o = 16; o > 0; o >>= 1) s += __shfl_xor_sync(0xffffffffu, s, o);
    if ((tid & 31) == 0) red[tid >> 5] = s;
    __syncthreads();
    s = ((red[0] + red[1]) + (red[2] + red[3])) + ((red[4] + red[5]) + (red[6] + red[7]));

    const float inv = 1.0f / s;
    v.x = rnd_tf32(v.x * inv); v.y = rnd_tf32(v.y * inv);
    v.z = rnd_tf32(v.z * inv); v.w = rnd_tf32(v.w * inv);
    reinterpret_cast<float4*>(p)[tid] = v;
}

// O = LayerNorm(X + Y); rows of 512; roundOut for outputs feeding GEMMs
__global__ __launch_bounds__(128)
void add_ln512(const float* __restrict__ X, const float* __restrict__ Y,
               const float* __restrict__ gamma, const float* __restrict__ beta,
               float* __restrict__ O, int roundOut)
{
    __shared__ float red[4];
    const long long row = blockIdx.x;
    const int tid = threadIdx.x;

    const float4 x4 = ((const float4*)(X + row * 512))[tid];
    const float4 y4 = ((const float4*)(Y + row * 512))[tid];
    float4 v;
    v.x = x4.x + y4.x; v.y = x4.y + y4.y; v.z = x4.z + y4.z; v.w = x4.w + y4.w;

    float s = (v.x + v.y) + (v.z + v.w);
    #pragma unroll
    for (int o = 16; o > 0; o >>= 1) s += __shfl_xor_sync(0xffffffffu, s, o);
    if ((tid & 31) == 0) red[tid >> 5] = s;
    __syncthreads();
    const float mean = ((red[0] + red[1]) + (red[2] + red[3])) * (1.0f / 512.0f);
    __syncthreads();

    float q = v.x * v.x + v.y * v.y + v.z * v.z + v.w * v.w;
    #pragma unroll
    for (int o = 16; o > 0; o >>= 1) q += __shfl_xor_sync(0xffffffffu, q, o);
    if ((tid & 31) == 0) red[tid >> 5] = q;
    __syncthreads();
    const float var = ((red[0] + red[1]) + (red[2] + red[3])) * (1.0f / 512.0f) - mean * mean;
    const float inv = rsqrtf(var + 1e-3f);

    const int n = tid * 4;
    const float4 g4 = *(const float4*)(gamma + n);
    const float4 b4 = *(const float4*)(beta + n);
    float4 o;
    o.x = g4.x * (v.x - mean) * inv + b4.x;
    o.y = g4.y * (v.y - mean) * inv + b4.y;
    o.z = g4.z * (v.z - mean) * inv + b4.z;
    o.w = g4.w * (v.w - mean) * inv + b4.w;
    if (roundOut) {
        o.x = rnd_tf32(o.x); o.y = rnd_tf32(o.y);
        o.z = rnd_tf32(o.z); o.w = rnd_tf32(o.w);
    }
    ((float4*)(O + row * 512))[tid] = o;
}

// ---------------------------------------------------------------------------

static void run_gemm(bool tb, const float* A, const float* B, float* C,
                     int M, int N, int K, int lda, int ldb, int ldc,
                     long long sA, long long sB,
                     int zdiv, long long sC1, long long sC2,
                     int batch, float alpha, const float* bias, int relu, int rOut)
{
    dim3 grid((N + BN - 1) / BN, M / BM, batch);
    if (tb)
        tf32_gemm<true><<<grid, 256, SMEM_BYTES>>>(A, B, C, M, N, K, lda, ldb, ldc,
            sA, sB, zdiv, sC1, sC2, alpha, bias, relu, rOut);
    else
        tf32_gemm<false><<<grid, 256, SMEM_BYTES>>>(A, B, C, M, N, K, lda, ldb, ldc,
            sA, sB, zdiv, sC1, sC2, alpha, bias, relu, rOut);
}

static void run_round(const float* src, float* dst, int n)
{
    int n4 = n / 4;
    round_copy<<<(n4 + 255) / 256, 256>>>((const float4*)src, (float4*)dst, n4);
}

struct Ptrs {
    float *q, *k, *v, *sc, *at, *mha, *h, *f1, *f2;
    float *xr, *qwr, *kwr, *vwr, *lwr, *w1r, *w2r;
};

static Ptrs get_ptrs()
{
    static Ptrs p;
    static bool init = false;
    if (!init) {
        cudaGetSymbolAddress((void**)&p.q,   g_q);
        cudaGetSymbolAddress((void**)&p.k,   g_k);
        cudaGetSymbolAddress((void**)&p.v,   g_v);
        cudaGetSymbolAddress((void**)&p.sc,  g_sc);
        cudaGetSymbolAddress((void**)&p.at,  g_at);
        cudaGetSymbolAddress((void**)&p.mha, g_mha);
        cudaGetSymbolAddress((void**)&p.h,   g_h);
        cudaGetSymbolAddress((void**)&p.f1,  g_f1);
        cudaGetSymbolAddress((void**)&p.f2,  g_f2);
        cudaGetSymbolAddress((void**)&p.xr,  g_xr);
        cudaGetSymbolAddress((void**)&p.qwr, g_qwr);
        cudaGetSymbolAddress((void**)&p.kwr, g_kwr);
        cudaGetSymbolAddress((void**)&p.vwr, g_vwr);
        cudaGetSymbolAddress((void**)&p.lwr, g_lwr);
        cudaGetSymbolAddress((void**)&p.w1r, g_w1r);
        cudaGetSymbolAddress((void**)&p.w2r, g_w2r);
        cudaFuncSetAttribute(tf32_gemm<true>,  cudaFuncAttributeMaxDynamicSharedMemorySize, SMEM_BYTES);
        cudaFuncSetAttribute(tf32_gemm<false>, cudaFuncAttributeMaxDynamicSharedMemorySize, SMEM_BYTES);
        init = true;
    }
    return p;
}

extern "C" void kernel_launch(void* const* d_in, const int* in_sizes, int n_in,
                              void* d_out, int out_size)
{
    const float* x      = (const float*)d_in[0];   // [8,1024,512]
    const float* qw     = (const float*)d_in[1];   // [8,512,64]
    const float* kw     = (const float*)d_in[2];   // [8,512,64]
    const float* vw     = (const float*)d_in[3];   // [8,512,512]
    const float* lw     = (const float*)d_in[4];   // [4096,512]
    const float* gamma1 = (const float*)d_in[5];
    const float* beta1  = (const float*)d_in[6];
    const float* w1     = (const float*)d_in[7];   // [512,2048]
    const float* b1     = (const float*)d_in[8];
    const float* w2     = (const float*)d_in[9];   // [2048,512]
    const float* b2     = (const float*)d_in[10];
    const float* gamma2 = (const float*)d_in[11];
    const float* beta2  = (const float*)d_in[12];
    float* out = (float*)d_out;

    Ptrs p = get_ptrs();
    const int M = 8192;
    const float scale = 0.044194173824159216f;  // 1/sqrt(512)

    // one-time tf32 rounding of raw inputs
    run_round(x,  p.xr,  4194304);
    run_round(qw, p.qwr, 262144);
    run_round(kw, p.kwr, 262144);
    run_round(vw, p.vwr, 2097152);
    run_round(lw, p.lwr, 2097152);
    run_round(w1, p.w1r, 1048576);
    run_round(w2, p.w2r, 1048576);

    // Q = x @ qw[h]  -> [H][8192][64]  (rounded out)
    run_gemm(false, p.xr, p.qwr, p.q, M, 64, 512, 512, 64, 64,
             0LL, 32768LL, 1, 524288LL, 0LL, 8, 1.0f, nullptr, 0, 1);
    // K
    run_gemm(false, p.xr, p.kwr, p.k, M, 64, 512, 512, 64, 64,
             0LL, 32768LL, 1, 524288LL, 0LL, 8, 1.0f, nullptr, 0, 1);
    // V -> [H][8192][512] (rounded out)
    run_gemm(false, p.xr, p.vwr, p.v, M, 512, 512, 512, 512, 512,
             0LL, 262144LL, 1, 4194304LL, 0LL, 8, 1.0f, nullptr, 0, 1);

    // scores[z] = scale * Q_z @ K_z^T (full fp32 out; softmax rounds probs)
    run_gemm(true, p.q, p.k, p.sc, 1024, 1024, 64, 64, 64, 1024,
             65536LL, 65536LL, 1, 1048576LL, 0LL, 64, scale, nullptr, 0, 0);

    softmax1024<<<65536, 256>>>(p.sc);

    // attn[z] = P_z @ V_z -> concat [8192][4096] (rounded out)
    run_gemm(false, p.sc, p.v, p.at, 1024, 512, 1024, 1024, 512, 4096,
             1048576LL, 524288LL, 8, 512LL, 4194304LL, 64, 1.0f, nullptr, 0, 1);

    // mha = attn @ lw (fp32)
    run_gemm(false, p.at, p.lwr, p.mha, M, 512, 4096, 4096, 512, 512,
             0LL, 0LL, 1, 0LL, 0LL, 1, 1.0f, nullptr, 0, 0);

    // h = LN(x + mha)  (rounded: feeds FFN1 GEMM)
    add_ln512<<<8192, 128>>>(x, p.mha, gamma1, beta1, p.h, 1);

    // f1 = relu(h @ w1 + b1) (rounded out)
    run_gemm(false, p.h, p.w1r, p.f1, M, 2048, 512, 512, 2048, 2048,
             0LL, 0LL, 1, 0LL, 0LL, 1, 1.0f, b1, 1, 1);
    // f2 = f1 @ w2 + b2 (fp32)
    run_gemm(false, p.f1, p.w2r, p.f2, M, 512, 2048, 2048, 512, 512,
             0LL, 0LL, 1, 0LL, 0LL, 1, 1.0f, b2, 0, 0);

    // out = LN(h + f2)
    add_ln512<<<8192, 128>>>(p.h, p.f2, gamma2, beta2, out, 0);
}

// round 10
// speedup vs baseline: 3.6756x; 1.0877x over previous
#include <cuda_runtime.h>
#include <cstdint>

// ---------------- scratch (device globals; no allocation allowed) -----------
__device__ float g_qk[8388608];    // [H][8192][128]  q(0:64) | k(64:128)
__device__ float g_v [33554432];   // [H][8192][512]
__device__ float g_sc[67108864];   // [64][1024][1024] E = exp(scale*s), tf32
__device__ float g_l [65536];      // [64][1024] row sums of E
__device__ float g_at[33554432];   // [8192][4096] concat heads
__device__ float g_mha[4194304];
__device__ float g_h [4194304];
__device__ float g_f1[16777216];   // [8192][2048]
__device__ float g_f2[4194304];
// tf32-rounded copies of raw inputs
__device__ float g_xr [4194304];
__device__ float g_qkw[524288];    // [8][512][128] concat qw|kw rounded
__device__ float g_vwr[2097152];
__device__ float g_lwr[2097152];
__device__ float g_w1r[1048576];
__device__ float g_w2r[1048576];

#define BM 128
#define BN 128
#define BK 32
#define ASTRF   36       // A smem row stride (floats): conflict-free
#define BSTRF_KM 136     // B smem row stride, k-major (floats)
#define A_BYTES 18432    // 128*36*4
#define STAGE   36864
#define SMEM_BYTES 73728

__device__ __forceinline__ void cp16(uint32_t dst, const void* src) {
    asm volatile("cp.async.cg.shared.global [%0], [%1], 16;" :: "r"(dst), "l"(src));
}
__device__ __forceinline__ void cp16z(uint32_t dst, const void* src) {
    asm volatile("cp.async.cg.shared.global [%0], [%1], 16, %2;"
                 :: "r"(dst), "l"(src), "r"(0));
}
__device__ __forceinline__ float rnd_tf32(float f) {
    uint32_t r;
    asm("cvt.rna.tf32.f32 %0, %1;" : "=r"(r) : "f"(f));
    return __uint_as_float(r);
}
__device__ __forceinline__ void mma_tf32(float* c, const uint32_t* a, const uint32_t* b) {
    asm volatile(
        "mma.sync.aligned.m16n8k8.row.col.f32.tf32.tf32.f32 "
        "{%0,%1,%2,%3},{%4,%5,%6,%7},{%8,%9},{%0,%1,%2,%3};"
        : "+f"(c[0]), "+f"(c[1]), "+f"(c[2]), "+f"(c[3])
        : "r"(a[0]), "r"(a[1]), "r"(a[2]), "r"(a[3]), "r"(b[0]), "r"(b[1]));
}

// C[m,n] (+z offsets) = alpha * sum_k A[m,k] * (TB ? B[n,k] : B[k,n]) (+bias)(relu)
// Operands must be tf32-rounded fp32 (raw bits feed MMA).
// rowsum!=0: epilogue stores tf32(exp(val)) and atomically accumulates row sums.
// rowdiv!=0: epilogue multiplies each row by 1/rowdiv[bz*rsStride + m].
template<bool TB>
__global__ __launch_bounds__(256, 2)
void tf32_gemm(const float* __restrict__ A, const float* __restrict__ B,
               float* __restrict__ C, int M, int N, int K,
               int lda, int ldb, int ldc,
               long long sA, long long sB,
               int zdiv, long long sC1, long long sC2,
               float alpha, const float* __restrict__ bias, int relu, int roundOut,
               float* rowsum, const float* __restrict__ rowdiv, int rsStride)
{
    extern __shared__ __align__(16) char dsm[];
    const uint32_t sBase = (uint32_t)__cvta_generic_to_shared(dsm);

    const int bz = blockIdx.z;
    A += (long long)bz * sA;
    B += (long long)bz * sB;
    const long long cOff = (long long)(bz / zdiv) * sC1 + (long long)(bz % zdiv) * sC2;

    const int mBase = blockIdx.y * BM;
    const int nBase = blockIdx.x * BN;
    const int tid   = threadIdx.x;
    const int lane  = tid & 31;
    const int warp  = tid >> 5;
    const int wm    = warp >> 2;
    const int wn    = warp & 3;
    const int g     = lane >> 2;
    const int tg    = lane & 3;

    float acc[4][4][4];
    #pragma unroll
    for (int i = 0; i < 4; i++)
        #pragma unroll
        for (int j = 0; j < 4; j++)
            #pragma unroll
            for (int e = 0; e < 4; e++) acc[i][j][e] = 0.0f;

    const int nk = K >> 5;

    auto load_tile = [&](int kt, int buf) {
        const int k0 = kt << 5;
        const uint32_t sb = sBase + buf * STAGE;
        #pragma unroll
        for (int it = 0; it < 4; it++) {
            int idx = tid + it * 256;
            int r = idx >> 3, c = idx & 7;
            cp16(sb + r * 144 + c * 16,
                 A + (long long)(mBase + r) * lda + k0 + c * 4);
        }
        if (TB) {
            #pragma unroll
            for (int it = 0; it < 4; it++) {
                int idx = tid + it * 256;
                int r = idx >> 3, c = idx & 7;
                int gn = nBase + r;
                uint32_t dst = sb + A_BYTES + r * 144 + c * 16;
                if (gn < N) cp16(dst, B + (long long)gn * ldb + k0 + c * 4);
                else        cp16z(dst, B);
            }
        } else {
            #pragma unroll
            for (int it = 0; it < 4; it++) {
                int idx = tid + it * 256;
                int r = idx >> 5, cc = idx & 31;
                int gn = nBase + cc * 4;
                uint32_t dst = sb + A_BYTES + r * 544 + cc * 16;
                if (gn < N) cp16(dst, B + (long long)(k0 + r) * ldb + gn);
                else        cp16z(dst, B);
            }
        }
        asm volatile("cp.async.commit_group;" ::: "memory");
    };

    load_tile(0, 0);

    for (int kt = 0; kt < nk; kt++) {
        if (kt + 1 < nk) {
            load_tile(kt + 1, (kt + 1) & 1);
            asm volatile("cp.async.wait_group 1;" ::: "memory");
        } else {
            asm volatile("cp.async.wait_group 0;" ::: "memory");
        }
        __syncthreads();

        const int buf = kt & 1;
        const uint32_t* As = (const uint32_t*)(dsm + buf * STAGE);
        const uint32_t* Bs = (const uint32_t*)(dsm + buf * STAGE + A_BYTES);

        #pragma unroll
        for (int ks = 0; ks < 4; ks++) {
            uint32_t bfr[4][2];
            #pragma unroll
            for (int ni = 0; ni < 4; ni++) {
                if (TB) {
                    int base = (wn * 32 + ni * 8 + g) * ASTRF + ks * 8 + tg;
                    bfr[ni][0] = Bs[base];
                    bfr[ni][1] = Bs[base + 4];
                } else {
                    int base = (ks * 8 + tg) * BSTRF_KM + wn * 32 + ni * 8 + g;
                    bfr[ni][0] = Bs[base];
                    bfr[ni][1] = Bs[base + 4 * BSTRF_KM];
                }
            }
            #pragma unroll
            for (int mi = 0; mi < 4; mi++) {
                int ab = (wm * 64 + mi * 16 + g) * ASTRF + ks * 8 + tg;
                uint32_t af[4];
                af[0] = As[ab];
                af[1] = As[ab + 8 * ASTRF];
                af[2] = As[ab + 4];
                af[3] = As[ab + 8 * ASTRF + 4];
                #pragma unroll
                for (int ni = 0; ni < 4; ni++)
                    mma_tf32(acc[mi][ni], af, bfr[ni]);
            }
        }
        __syncthreads();
    }

    // ---- epilogue ----
    float rdInv[4][2];
    if (rowdiv) {
        #pragma unroll
        for (int mi = 0; mi < 4; mi++)
            #pragma unroll
            for (int rr = 0; rr < 2; rr++) {
                long long m = mBase + wm * 64 + mi * 16 + g + rr * 8;
                rdInv[mi][rr] = 1.0f / rowdiv[(long long)bz * rsStride + m];
            }
    }
    #pragma unroll
    for (int mi = 0; mi < 4; mi++) {
        float rs0 = 0.f, rs1 = 0.f;
        #pragma unroll
        for (int ni = 0; ni < 4; ni++) {
            int n = nBase + wn * 32 + ni * 8 + tg * 2;
            if (n < N) {
                float bx = 0.f, by = 0.f;
                if (bias) { bx = bias[n]; by = bias[n + 1]; }
                #pragma unroll
                for (int rr = 0; rr < 2; rr++) {
                    int m = mBase + wm * 64 + mi * 16 + g + rr * 8;
                    float ox = acc[mi][ni][rr * 2 + 0] * alpha + bx;
                    float oy = acc[mi][ni][rr * 2 + 1] * alpha + by;
                    if (relu) { ox = fmaxf(ox, 0.f); oy = fmaxf(oy, 0.f); }
                    if (rowsum) {
                        ox = rnd_tf32(__expf(ox));
                        oy = rnd_tf32(__expf(oy));
                        if (rr == 0) rs0 += ox + oy; else rs1 += ox + oy;
                    } else {
                        if (rowdiv)   { ox *= rdInv[mi][rr]; oy *= rdInv[mi][rr]; }
                        if (roundOut) { ox = rnd_tf32(ox);   oy = rnd_tf32(oy); }
                    }
                    *(float2*)(C + cOff + (long long)m * ldc + n) = make_float2(ox, oy);
                }
            }
        }
        if (rowsum) {
            rs0 += __shfl_xor_sync(0xffffffffu, rs0, 1);
            rs0 += __shfl_xor_sync(0xffffffffu, rs0, 2);
            rs1 += __shfl_xor_sync(0xffffffffu, rs1, 1);
            rs1 += __shfl_xor_sync(0xffffffffu, rs1, 2);
            if (tg == 0) {
                long long m0 = mBase + wm * 64 + mi * 16 + g;
                atomicAdd(rowsum + (long long)bz * rsStride + m0,     rs0);
                atomicAdd(rowsum + (long long)bz * rsStride + m0 + 8, rs1);
            }
        }
    }
}

// tf32-round copy
__global__ __launch_bounds__(256)
void round_copy(const float4* __restrict__ src, float4* __restrict__ dst, int n4)
{
    int i = blockIdx.x * 256 + threadIdx.x;
    if (i < n4) {
        float4 v = src[i];
        v.x = rnd_tf32(v.x); v.y = rnd_tf32(v.y);
        v.z = rnd_tf32(v.z); v.w = rnd_tf32(v.w);
        dst[i] = v;
    }
}

// round + copy [rows][64] into [rows][128] at column offset
__global__ __launch_bounds__(256)
void round_concat(const float4* __restrict__ src, float* __restrict__ dst,
                  int n4, int colOff)
{
    int i = blockIdx.x * 256 + threadIdx.x;
    if (i < n4) {
        float4 v = src[i];
        v.x = rnd_tf32(v.x); v.y = rnd_tf32(v.y);
        v.z = rnd_tf32(v.z); v.w = rnd_tf32(v.w);
        int row = i >> 4;            // 16 float4 per 64-col row
        int c4  = i & 15;
        *(float4*)(dst + (long long)row * 128 + colOff + c4 * 4) = v;
    }
}

__global__ __launch_bounds__(256)
void zero_kernel(float* __restrict__ p, int n)
{
    int i = blockIdx.x * 256 + threadIdx.x;
    if (i < n) p[i] = 0.0f;
}

// O = LayerNorm(X + Y); rows of 512
__global__ __launch_bounds__(128)
void add_ln512(const float* __restrict__ X, const float* __restrict__ Y,
               const float* __restrict__ gamma, const float* __restrict__ beta,
               float* __restrict__ O, int roundOut)
{
    __shared__ float red[4];
    const long long row = blockIdx.x;
    const int tid = threadIdx.x;

    const float4 x4 = ((const float4*)(X + row * 512))[tid];
    const float4 y4 = ((const float4*)(Y + row * 512))[tid];
    float4 v;
    v.x = x4.x + y4.x; v.y = x4.y + y4.y; v.z = x4.z + y4.z; v.w = x4.w + y4.w;

    float s = (v.x + v.y) + (v.z + v.w);
    #pragma unroll
    for (int o = 16; o > 0; o >>= 1) s += __shfl_xor_sync(0xffffffffu, s, o);
    if ((tid & 31) == 0) red[tid >> 5] = s;
    __syncthreads();
    const float mean = ((red[0] + red[1]) + (red[2] + red[3])) * (1.0f / 512.0f);
    __syncthreads();

    float q = v.x * v.x + v.y * v.y + v.z * v.z + v.w * v.w;
    #pragma unroll
    for (int o = 16; o > 0; o >>= 1) q += __shfl_xor_sync(0xffffffffu, q, o);
    if ((tid & 31) == 0) red[tid >> 5] = q;
    __syncthreads();
    const float var = ((red[0] + red[1]) + (red[2] + red[3])) * (1.0f / 512.0f) - mean * mean;
    const float inv = rsqrtf(var + 1e-3f);

    const int n = tid * 4;
    const float4 g4 = *(const float4*)(gamma + n);
    const float4 b4 = *(const float4*)(beta + n);
    float4 o;
    o.x = g4.x * (v.x - mean) * inv + b4.x;
    o.y = g4.y * (v.y - mean) * inv + b4.y;
    o.z = g4.z * (v.z - mean) * inv + b4.z;
    o.w = g4.w * (v.w - mean) * inv + b4.w;
    if (roundOut) {
        o.x = rnd_tf32(o.x); o.y = rnd_tf32(o.y);
        o.z = rnd_tf32(o.z); o.w = rnd_tf32(o.w);
    }
    ((float4*)(O + row * 512))[tid] = o;
}

// ---------------------------------------------------------------------------

static void run_gemm(bool tb, const float* A, const float* B, float* C,
                     int M, int N, int K, int lda, int ldb, int ldc,
                     long long sA, long long sB,
                     int zdiv, long long sC1, long long sC2,
                     int batch, float alpha, const float* bias, int relu, int rOut,
                     float* rowsum = nullptr, const float* rowdiv = nullptr,
                     int rsStride = 0)
{
    dim3 grid((N + BN - 1) / BN, M / BM, batch);
    if (tb)
        tf32_gemm<true><<<grid, 256, SMEM_BYTES>>>(A, B, C, M, N, K, lda, ldb, ldc,
            sA, sB, zdiv, sC1, sC2, alpha, bias, relu, rOut, rowsum, rowdiv, rsStride);
    else
        tf32_gemm<false><<<grid, 256, SMEM_BYTES>>>(A, B, C, M, N, K, lda, ldb, ldc,
            sA, sB, zdiv, sC1, sC2, alpha, bias, relu, rOut, rowsum, rowdiv, rsStride);
}

static void run_round(const float* src, float* dst, int n)
{
    int n4 = n / 4;
    round_copy<<<(n4 + 255) / 256, 256>>>((const float4*)src, (float4*)dst, n4);
}

struct Ptrs {
    float *qk, *v, *sc, *l, *at, *mha, *h, *f1, *f2;
    float *xr, *qkw, *vwr, *lwr, *w1r, *w2r;
};

static Ptrs get_ptrs()
{
    static Ptrs p;
    static bool init = false;
    if (!init) {
        cudaGetSymbolAddress((void**)&p.qk,  g_qk);
        cudaGetSymbolAddress((void**)&p.v,   g_v);
        cudaGetSymbolAddress((void**)&p.sc,  g_sc);
        cudaGetSymbolAddress((void**)&p.l,   g_l);
        cudaGetSymbolAddress((void**)&p.at,  g_at);
        cudaGetSymbolAddress((void**)&p.mha, g_mha);
        cudaGetSymbolAddress((void**)&p.h,   g_h);
        cudaGetSymbolAddress((void**)&p.f1,  g_f1);
        cudaGetSymbolAddress((void**)&p.f2,  g_f2);
        cudaGetSymbolAddress((void**)&p.xr,  g_xr);
        cudaGetSymbolAddress((void**)&p.qkw, g_qkw);
        cudaGetSymbolAddress((void**)&p.vwr, g_vwr);
        cudaGetSymbolAddress((void**)&p.lwr, g_lwr);
        cudaGetSymbolAddress((void**)&p.w1r, g_w1r);
        cudaGetSymbolAddress((void**)&p.w2r, g_w2r);
        cudaFuncSetAttribute(tf32_gemm<true>,  cudaFuncAttributeMaxDynamicSharedMemorySize, SMEM_BYTES);
        cudaFuncSetAttribute(tf32_gemm<false>, cudaFuncAttributeMaxDynamicSharedMemorySize, SMEM_BYTES);
        init = true;
    }
    return p;
}

extern "C" void kernel_launch(void* const* d_in, const int* in_sizes, int n_in,
                              void* d_out, int out_size)
{
    const float* x      = (const float*)d_in[0];   // [8,1024,512]
    const float* qw     = (const float*)d_in[1];   // [8,512,64]
    const float* kw     = (const float*)d_in[2];   // [8,512,64]
    const float* vw     = (const float*)d_in[3];   // [8,512,512]
    const float* lw     = (const float*)d_in[4];   // [4096,512]
    const float* gamma1 = (const float*)d_in[5];
    const float* beta1  = (const float*)d_in[6];
    const float* w1     = (const float*)d_in[7];   // [512,2048]
    const float* b1     = (const float*)d_in[8];
    const float* w2     = (const float*)d_in[9];   // [2048,512]
    const float* b2     = (const float*)d_in[10];
    const float* gamma2 = (const float*)d_in[11];
    const float* beta2  = (const float*)d_in[12];
    float* out = (float*)d_out;

    Ptrs p = get_ptrs();
    const int M = 8192;
    const float scale = 0.044194173824159216f;  // 1/sqrt(512)

    // zero row-sum accumulator (re-zeroed every replay; part of graph)
    zero_kernel<<<256, 256>>>(p.l, 65536);

    // one-time tf32 rounding of raw inputs; qw|kw concatenated to [8][512][128]
    run_round(x,  p.xr,  4194304);
    round_concat<<<(65536 + 255) / 256, 256>>>((const float4*)qw, p.qkw, 65536, 0);
    round_concat<<<(65536 + 255) / 256, 256>>>((const float4*)kw, p.qkw, 65536, 64);
    run_round(vw, p.vwr, 2097152);
    run_round(lw, p.lwr, 2097152);
    run_round(w1, p.w1r, 1048576);
    run_round(w2, p.w2r, 1048576);

    // QK = x @ [qw|kw][h] -> [H][8192][128] (rounded out)
    run_gemm(false, p.xr, p.qkw, p.qk, M, 128, 512, 512, 128, 128,
             0LL, 65536LL, 1, 1048576LL, 0LL, 8, 1.0f, nullptr, 0, 1);
    // V = x @ vw[h] -> [H][8192][512] (rounded out)
    run_gemm(false, p.xr, p.vwr, p.v, M, 512, 512, 512, 512, 512,
             0LL, 262144LL, 1, 4194304LL, 0LL, 8, 1.0f, nullptr, 0, 1);

    // E[z] = exp(scale * Q_z @ K_z^T) + row sums into g_l (z = h*8+b)
    // q slice: g_qk + z*131072 cols 0:64 ; k slice: +64
    run_gemm(true, p.qk, p.qk + 64, p.sc, 1024, 1024, 64, 128, 128, 1024,
             131072LL, 131072LL, 1, 1048576LL, 0LL, 64, scale, nullptr, 0, 0,
             p.l, nullptr, 1024);

    // attn[z] = (E_z @ V_z) / l -> concat [8192][4096] (rounded out)
    run_gemm(false, p.sc, p.v, p.at, 1024, 512, 1024, 1024, 512, 4096,
             1048576LL, 524288LL, 8, 512LL, 4194304LL, 64, 1.0f, nullptr, 0, 1,
             nullptr, p.l, 1024);

    // mha = attn @ lw (fp32)
    run_gemm(false, p.at, p.lwr, p.mha, M, 512, 4096, 4096, 512, 512,
             0LL, 0LL, 1, 0LL, 0LL, 1, 1.0f, nullptr, 0, 0);

    // h = LN(x + mha)  (rounded: feeds FFN1 GEMM)
    add_ln512<<<8192, 128>>>(x, p.mha, gamma1, beta1, p.h, 1);

    // f1 = relu(h @ w1 + b1) (rounded out)
    run_gemm(false, p.h, p.w1r, p.f1, M, 2048, 512, 512, 2048, 2048,
             0LL, 0LL, 1, 0LL, 0LL, 1, 1.0f, b1, 1, 1);
    // f2 = f1 @ w2 + b2 (fp32)
    run_gemm(false, p.f1, p.w2r, p.f2, M, 512, 2048, 2048, 512, 512,
             0LL, 0LL, 1, 0LL, 0LL, 1, 1.0f, b2, 0, 0);

    // out = LN(h + f2)
    add_ln512<<<8192, 128>>>(p.h, p.f2, gamma2, beta2, out, 0);
}